// round 1
// baseline (speedup 1.0000x reference)
#include <cuda_runtime.h>
#include <cstdint>

#define NN 50000
#define EE 800000
#define BB 256
#define FEAT 128
#define OUTC 10
#define EPSBN 1e-5f

// ---------------- static scratch (device globals; no allocation) ----------------
__device__ float g_hs[NN * FEAT];   // GEMM output, pre-scaled by dout^-1/2 (gather source)
__device__ float g_h1[NN * FEAT];   // layer-1 output
__device__ float g_h2[NN * FEAT];   // layer-2 output
__device__ int g_deg_out[NN];
__device__ int g_deg_in[NN];
__device__ int g_row[NN];           // CSR row start (by dst)
__device__ int g_cur[NN];           // scatter cursors
__device__ int g_csr[EE];           // src ids sorted by dst

// ---------------- small utility kernels ----------------
__global__ void zero_float_kernel(float* p, int n) {
    int i = blockIdx.x * blockDim.x + threadIdx.x;
    if (i < n) p[i] = 0.0f;
}

__global__ void zero_deg_kernel() {
    int i = blockIdx.x * blockDim.x + threadIdx.x;
    if (i < NN) { g_deg_out[i] = 0; g_deg_in[i] = 0; }
}

__global__ void degree_kernel(const int* __restrict__ src, const int* __restrict__ dst) {
    int i = blockIdx.x * blockDim.x + threadIdx.x;
    if (i < EE) {
        atomicAdd(&g_deg_out[src[i]], 1);
        atomicAdd(&g_deg_in[dst[i]], 1);
    }
}

// single-block exclusive scan of g_deg_in -> g_row ; also zeroes g_cur
__global__ void scan_kernel() {
    __shared__ int sm[1024];
    int t = threadIdx.x;
    int carry = 0;
    for (int base = 0; base < NN; base += 1024) {
        int idx = base + t;
        int v = (idx < NN) ? g_deg_in[idx] : 0;
        sm[t] = v;
        __syncthreads();
        int x = v;
        #pragma unroll
        for (int off = 1; off < 1024; off <<= 1) {
            int y = (t >= off) ? sm[t - off] : 0;
            __syncthreads();
            x += y;
            sm[t] = x;
            __syncthreads();
        }
        if (idx < NN) {
            g_row[idx] = carry + x - v;   // exclusive
            g_cur[idx] = 0;
        }
        int tot = sm[1023];
        __syncthreads();
        carry += tot;
    }
}

__global__ void scatter_kernel(const int* __restrict__ src, const int* __restrict__ dst) {
    int i = blockIdx.x * blockDim.x + threadIdx.x;
    if (i < EE) {
        int d = dst[i];
        int pos = g_row[d] + atomicAdd(&g_cur[d], 1);
        g_csr[pos] = src[i];
    }
}

// ---------------- GEMM: out[m,:] = (A[m,:] @ W) * rsqrt(max(deg_out[m],1)) ----------------
// A: [nrows,128] row-major, W: [128,128] row-major. BM=BN=128, BK=8, 256 thr, 8x8 per thread.
__global__ __launch_bounds__(256) void gemm_scale_kernel(
    const float* __restrict__ A, const float* __restrict__ W,
    float* __restrict__ out, int nrows)
{
    __shared__ float As[8][129];
    __shared__ float Bs[8][128];
    int tid = threadIdx.x;
    int tx = tid & 15;
    int ty = tid >> 4;
    int row0 = blockIdx.x * 128;

    float acc[8][8];
    #pragma unroll
    for (int i = 0; i < 8; i++)
        #pragma unroll
        for (int j = 0; j < 8; j++) acc[i][j] = 0.0f;

    int am = tid >> 1;           // 0..127
    int ak = (tid & 1) * 4;      // 0 or 4
    int bk = tid >> 5;           // 0..7
    int bn = (tid & 31) * 4;     // 0..124

    for (int k0 = 0; k0 < 128; k0 += 8) {
        int gr = row0 + am;
        float4 av = make_float4(0.f, 0.f, 0.f, 0.f);
        if (gr < nrows) av = *reinterpret_cast<const float4*>(A + (size_t)gr * 128 + k0 + ak);
        As[ak + 0][am] = av.x;
        As[ak + 1][am] = av.y;
        As[ak + 2][am] = av.z;
        As[ak + 3][am] = av.w;
        float4 bv = *reinterpret_cast<const float4*>(W + (size_t)(k0 + bk) * 128 + bn);
        *reinterpret_cast<float4*>(&Bs[bk][bn]) = bv;
        __syncthreads();

        #pragma unroll
        for (int k = 0; k < 8; k++) {
            float rm[8];
            #pragma unroll
            for (int i = 0; i < 8; i++) rm[i] = As[k][ty * 8 + i];
            float4 rn0 = *reinterpret_cast<const float4*>(&Bs[k][tx * 8]);
            float4 rn1 = *reinterpret_cast<const float4*>(&Bs[k][tx * 8 + 4]);
            float rn[8] = {rn0.x, rn0.y, rn0.z, rn0.w, rn1.x, rn1.y, rn1.z, rn1.w};
            #pragma unroll
            for (int i = 0; i < 8; i++)
                #pragma unroll
                for (int j = 0; j < 8; j++)
                    acc[i][j] = fmaf(rm[i], rn[j], acc[i][j]);
        }
        __syncthreads();
    }

    #pragma unroll
    for (int i = 0; i < 8; i++) {
        int r = row0 + ty * 8 + i;
        if (r < nrows) {
            int dg = g_deg_out[r];
            float rs = rsqrtf((float)(dg > 0 ? dg : 1));
            float4 o0, o1;
            o0.x = acc[i][0] * rs; o0.y = acc[i][1] * rs;
            o0.z = acc[i][2] * rs; o0.w = acc[i][3] * rs;
            o1.x = acc[i][4] * rs; o1.y = acc[i][5] * rs;
            o1.z = acc[i][6] * rs; o1.w = acc[i][7] * rs;
            float* op = out + (size_t)r * 128 + tx * 8;
            *reinterpret_cast<float4*>(op) = o0;
            *reinterpret_cast<float4*>(op + 4) = o1;
        }
    }
}

// ---------------- SpMM gather: out[i] = relu((sum_{e in csr[i]} hs[src_e]) * din^-1/2 + b) ----------------
// one warp per dst node; lane covers 4 feats via float4
__global__ __launch_bounds__(256) void spmm_kernel(const float* __restrict__ bias,
                                                   float* __restrict__ out)
{
    int warp = (blockIdx.x * blockDim.x + threadIdx.x) >> 5;
    int lane = threadIdx.x & 31;
    if (warp >= NN) return;
    int start = g_row[warp];
    int d = g_deg_in[warp];
    const float4* hs4 = reinterpret_cast<const float4*>(g_hs);
    float ax = 0.f, ay = 0.f, az = 0.f, aw = 0.f;
    int e = 0;
    for (; e + 2 <= d; e += 2) {
        int s0 = g_csr[start + e];
        int s1 = g_csr[start + e + 1];
        float4 v0 = hs4[(size_t)s0 * 32 + lane];
        float4 v1 = hs4[(size_t)s1 * 32 + lane];
        ax += v0.x + v1.x; ay += v0.y + v1.y;
        az += v0.z + v1.z; aw += v0.w + v1.w;
    }
    if (e < d) {
        int s = g_csr[start + e];
        float4 v = hs4[(size_t)s * 32 + lane];
        ax += v.x; ay += v.y; az += v.z; aw += v.w;
    }
    float rs = rsqrtf((float)(d > 0 ? d : 1));
    float4 bb = reinterpret_cast<const float4*>(bias)[lane];
    float4 r;
    r.x = fmaxf(fmaf(ax, rs, bb.x), 0.f);
    r.y = fmaxf(fmaf(ay, rs, bb.y), 0.f);
    r.z = fmaxf(fmaf(az, rs, bb.z), 0.f);
    r.w = fmaxf(fmaf(aw, rs, bb.w), 0.f);
    reinterpret_cast<float4*>(out)[(size_t)warp * 32 + lane] = r;
}

// ---------------- SumPooling: emb[gid[n], col_off + f] += h2[n, f] (gid sorted -> run-length) ----------------
#define POOL_CHUNK 64
__global__ void pool_kernel(const float* __restrict__ h2, const int* __restrict__ gid,
                            float* __restrict__ emb, int col_off)
{
    int f = threadIdx.x;                       // 0..127
    int n0 = blockIdx.x * POOL_CHUNK;
    int n1 = n0 + POOL_CHUNK; if (n1 > NN) n1 = NN;
    if (n0 >= NN) return;
    float local = 0.f;
    int g = gid[n0];
    for (int n = n0; n < n1; n++) {
        int gn = gid[n];
        if (gn != g) {
            atomicAdd(&emb[(size_t)g * 384 + col_off + f], local);
            local = 0.f;
            g = gn;
        }
        local += h2[(size_t)n * 128 + f];
    }
    atomicAdd(&emb[(size_t)g * 384 + col_off + f], local);
}

// ---------------- Head: BN -> fc1 -> relu -> fc2 -> log_softmax ----------------
__global__ __launch_bounds__(128) void head_kernel(
    const float* __restrict__ emb,
    const float* __restrict__ gamma, const float* __restrict__ beta,
    const float* __restrict__ mean, const float* __restrict__ var,
    const float* __restrict__ fc1W, const float* __restrict__ fc1b,
    const float* __restrict__ fc2W, const float* __restrict__ fc2b,
    float* __restrict__ outlp)
{
    __shared__ float s[384];
    __shared__ float h[128];
    __shared__ float lg[OUTC];
    int b = blockIdx.x;
    int t = threadIdx.x;
    for (int i = t; i < 384; i += 128) {
        float v = emb[(size_t)b * 384 + i];
        s[i] = (v - mean[i]) * rsqrtf(var[i] + EPSBN) * gamma[i] + beta[i];
    }
    __syncthreads();
    float acc = fc1b[t];
    #pragma unroll 4
    for (int k = 0; k < 384; k++) acc = fmaf(s[k], fc1W[(size_t)k * 128 + t], acc);
    h[t] = fmaxf(acc, 0.f);
    __syncthreads();
    if (t < OUTC) {
        float a = fc2b[t];
        #pragma unroll 4
        for (int k = 0; k < 128; k++) a = fmaf(h[k], fc2W[(size_t)k * OUTC + t], a);
        lg[t] = a;
    }
    __syncthreads();
    if (t == 0) {
        float mx = lg[0];
        #pragma unroll
        for (int o = 1; o < OUTC; o++) mx = fmaxf(mx, lg[o]);
        float se = 0.f;
        #pragma unroll
        for (int o = 0; o < OUTC; o++) se += expf(lg[o] - mx);
        float lse = mx + logf(se);
        #pragma unroll
        for (int o = 0; o < OUTC; o++) outlp[(size_t)b * OUTC + o] = lg[o] - lse;
    }
}

// ---------------- launch ----------------
extern "C" void kernel_launch(void* const* d_in, const int* in_sizes, int n_in,
                              void* d_out, int out_size)
{
    const float* x[3];
    const int* src[3];
    const int* dst[3];
    const int* gid[3];

    // Input ordering: dict order (x1,src1,dst1,gid1,...) vs signature order (x1,x2,x3,src1,dst1,...)
    if (in_sizes[1] == EE) {
        for (int g = 0; g < 3; g++) {
            x[g]   = (const float*)d_in[4 * g + 0];
            src[g] = (const int*)  d_in[4 * g + 1];
            dst[g] = (const int*)  d_in[4 * g + 2];
            gid[g] = (const int*)  d_in[4 * g + 3];
        }
    } else {
        for (int g = 0; g < 3; g++) {
            x[g]   = (const float*)d_in[g];
            src[g] = (const int*)  d_in[3 + 2 * g];
            dst[g] = (const int*)  d_in[4 + 2 * g];
            gid[g] = (const int*)  d_in[9 + g];
        }
    }
    const float* W1   = (const float*)d_in[12];
    const float* b1   = (const float*)d_in[13];
    const float* W2   = (const float*)d_in[14];
    const float* b2   = (const float*)d_in[15];
    const float* gma  = (const float*)d_in[16];
    const float* bta  = (const float*)d_in[17];
    const float* mean = (const float*)d_in[18];
    const float* var  = (const float*)d_in[19];
    const float* f1W  = (const float*)d_in[20];
    const float* f1b  = (const float*)d_in[21];
    const float* f2W  = (const float*)d_in[22];
    const float* f2b  = (const float*)d_in[23];

    float* out = (float*)d_out;
    float* emb = out;                    // [256, 384]
    float* lp  = out + (size_t)BB * 384; // [256, 10]

    // pointers to device-global scratch via symbols (device code uses them directly)
    float* hs_p; float* h1_p; float* h2_p;
    cudaGetSymbolAddress((void**)&hs_p, g_hs);
    cudaGetSymbolAddress((void**)&h1_p, g_h1);
    cudaGetSymbolAddress((void**)&h2_p, g_h2);

    zero_float_kernel<<<(BB * 384 + 255) / 256, 256>>>(emb, BB * 384);

    const int gemm_blocks = (NN + 127) / 128;
    const int spmm_blocks = (NN + 7) / 8;          // 8 warps/block
    const int pool_blocks = (NN + POOL_CHUNK - 1) / POOL_CHUNK;

    for (int g = 0; g < 3; g++) {
        zero_deg_kernel<<<(NN + 255) / 256, 256>>>();
        degree_kernel<<<(EE + 255) / 256, 256>>>(src[g], dst[g]);
        scan_kernel<<<1, 1024>>>();
        scatter_kernel<<<(EE + 255) / 256, 256>>>(src[g], dst[g]);

        // layer 1
        gemm_scale_kernel<<<gemm_blocks, 256>>>(x[g], W1, hs_p, NN);
        spmm_kernel<<<spmm_blocks, 256>>>(b1, h1_p);
        // layer 2
        gemm_scale_kernel<<<gemm_blocks, 256>>>(h1_p, W2, hs_p, NN);
        spmm_kernel<<<spmm_blocks, 256>>>(b2, h2_p);

        pool_kernel<<<pool_blocks, 128>>>(h2_p, gid[g], emb, g * 128);
    }

    head_kernel<<<BB, 128>>>(emb, gma, bta, mean, var, f1W, f1b, f2W, f2b, lp);
}

// round 2
// speedup vs baseline: 1.4041x; 1.4041x over previous
#include <cuda_runtime.h>
#include <cstdint>

#define NN 50000
#define EE 800000
#define BB 256
#define FEAT 128
#define OUTC 10
#define EPSBN 1e-5f
#define SCAN_BLK 1024
#define NSCAN_BLOCKS ((NN + SCAN_BLK - 1) / SCAN_BLK)   // 49

// ---------------- static scratch (device globals; no allocation) ----------------
__device__ float g_hs[NN * FEAT];   // GEMM output, pre-scaled by dout^-1/2 (gather source)
__device__ float g_h1[NN * FEAT];   // layer-1 output
__device__ float g_h2[NN * FEAT];   // layer-2 output
__device__ int g_deg_out[NN];
__device__ int g_deg_in[NN];
__device__ int g_row[NN];           // CSR row start (by dst)
__device__ int g_cur[NN];           // scatter cursors
__device__ int g_csr[EE];           // src ids sorted by dst
__device__ int g_bsum[NSCAN_BLOCKS];

// ---------------- small utility kernels ----------------
__global__ void zero_float_kernel(float* p, int n) {
    int i = blockIdx.x * blockDim.x + threadIdx.x;
    if (i < n) p[i] = 0.0f;
}

__global__ void zero_deg_kernel() {
    int i = blockIdx.x * blockDim.x + threadIdx.x;
    if (i < NN) { g_deg_out[i] = 0; g_deg_in[i] = 0; }
}

__global__ void degree_kernel(const int* __restrict__ src, const int* __restrict__ dst) {
    int i = blockIdx.x * blockDim.x + threadIdx.x;
    if (i < EE) {
        atomicAdd(&g_deg_out[src[i]], 1);
        atomicAdd(&g_deg_in[dst[i]], 1);
    }
}

// ---- multi-block exclusive scan of g_deg_in -> g_row ----
// pass 1: per-block local exclusive scan, block total -> g_bsum
__global__ __launch_bounds__(SCAN_BLK) void scan_local_kernel() {
    __shared__ int sm[SCAN_BLK];
    int t = threadIdx.x;
    int idx = blockIdx.x * SCAN_BLK + t;
    int v = (idx < NN) ? g_deg_in[idx] : 0;
    sm[t] = v;
    __syncthreads();
    #pragma unroll
    for (int off = 1; off < SCAN_BLK; off <<= 1) {
        int y = (t >= off) ? sm[t - off] : 0;
        __syncthreads();
        sm[t] += y;
        __syncthreads();
    }
    if (idx < NN) g_row[idx] = sm[t] - v;     // local exclusive
    if (t == SCAN_BLK - 1) g_bsum[blockIdx.x] = sm[t];
}

// pass 2: tiny serial scan of the 49 block sums (single thread; 49 adds)
__global__ void scan_bsum_kernel() {
    if (threadIdx.x == 0) {
        int run = 0;
        #pragma unroll 1
        for (int i = 0; i < NSCAN_BLOCKS; i++) {
            int tmp = g_bsum[i];
            g_bsum[i] = run;
            run += tmp;
        }
    }
}

// pass 3: add block offset; also zero cursors
__global__ __launch_bounds__(SCAN_BLK) void scan_add_kernel() {
    int idx = blockIdx.x * SCAN_BLK + threadIdx.x;
    if (idx < NN) {
        g_row[idx] += g_bsum[blockIdx.x];
        g_cur[idx] = 0;
    }
}

__global__ void scatter_kernel(const int* __restrict__ src, const int* __restrict__ dst) {
    int i = blockIdx.x * blockDim.x + threadIdx.x;
    if (i < EE) {
        int d = dst[i];
        int pos = g_row[d] + atomicAdd(&g_cur[d], 1);
        g_csr[pos] = src[i];
    }
}

// ---------------- GEMM: out[m,:] = (A[m,:] @ W) * rsqrt(max(deg_out[m],1)) ----------------
// A: [nrows,128] row-major, W: [128,128] row-major. BM=BN=128, BK=32, 256 thr, 8x8 per thread.
__global__ __launch_bounds__(256) void gemm_scale_kernel(
    const float* __restrict__ A, const float* __restrict__ W,
    float* __restrict__ out, int nrows)
{
    __shared__ float As[32][129];
    __shared__ float Bs[32][128];
    int tid = threadIdx.x;
    int tx = tid & 15;
    int ty = tid >> 4;
    int row0 = blockIdx.x * 128;

    float acc[8][8];
    #pragma unroll
    for (int i = 0; i < 8; i++)
        #pragma unroll
        for (int j = 0; j < 8; j++) acc[i][j] = 0.0f;

    for (int k0 = 0; k0 < 128; k0 += 32) {
        // load A tile: 128 rows x 32 cols = 1024 float4 loads, 4 per thread
        #pragma unroll
        for (int rep = 0; rep < 4; rep++) {
            int idx = tid + rep * 256;           // 0..1023
            int am = idx >> 3;                   // 0..127
            int ak = (idx & 7) * 4;              // 0,4,...,28
            int gr = row0 + am;
            float4 av = make_float4(0.f, 0.f, 0.f, 0.f);
            if (gr < nrows) av = *reinterpret_cast<const float4*>(A + (size_t)gr * 128 + k0 + ak);
            As[ak + 0][am] = av.x;
            As[ak + 1][am] = av.y;
            As[ak + 2][am] = av.z;
            As[ak + 3][am] = av.w;
        }
        // load W tile: 32 rows x 128 cols = 1024 float4, 4 per thread
        #pragma unroll
        for (int rep = 0; rep < 4; rep++) {
            int idx = tid + rep * 256;
            int bk = idx >> 5;                   // 0..31
            int bn = (idx & 31) * 4;             // 0..124
            float4 bv = *reinterpret_cast<const float4*>(W + (size_t)(k0 + bk) * 128 + bn);
            *reinterpret_cast<float4*>(&Bs[bk][bn]) = bv;
        }
        __syncthreads();

        #pragma unroll
        for (int k = 0; k < 32; k++) {
            float rm[8];
            #pragma unroll
            for (int i = 0; i < 8; i++) rm[i] = As[k][ty * 8 + i];
            float4 rn0 = *reinterpret_cast<const float4*>(&Bs[k][tx * 8]);
            float4 rn1 = *reinterpret_cast<const float4*>(&Bs[k][tx * 8 + 4]);
            float rn[8] = {rn0.x, rn0.y, rn0.z, rn0.w, rn1.x, rn1.y, rn1.z, rn1.w};
            #pragma unroll
            for (int i = 0; i < 8; i++)
                #pragma unroll
                for (int j = 0; j < 8; j++)
                    acc[i][j] = fmaf(rm[i], rn[j], acc[i][j]);
        }
        __syncthreads();
    }

    #pragma unroll
    for (int i = 0; i < 8; i++) {
        int r = row0 + ty * 8 + i;
        if (r < nrows) {
            int dg = g_deg_out[r];
            float rs = rsqrtf((float)(dg > 0 ? dg : 1));
            float4 o0, o1;
            o0.x = acc[i][0] * rs; o0.y = acc[i][1] * rs;
            o0.z = acc[i][2] * rs; o0.w = acc[i][3] * rs;
            o1.x = acc[i][4] * rs; o1.y = acc[i][5] * rs;
            o1.z = acc[i][6] * rs; o1.w = acc[i][7] * rs;
            float* op = out + (size_t)r * 128 + tx * 8;
            *reinterpret_cast<float4*>(op) = o0;
            *reinterpret_cast<float4*>(op + 4) = o1;
        }
    }
}

// ---------------- SpMM gather: out[i] = relu((sum_{e in csr[i]} hs[src_e]) * din^-1/2 + b) ----------------
// one warp per dst node; lane covers 4 feats via float4
__global__ __launch_bounds__(256) void spmm_kernel(const float* __restrict__ bias,
                                                   float* __restrict__ out)
{
    int warp = (blockIdx.x * blockDim.x + threadIdx.x) >> 5;
    int lane = threadIdx.x & 31;
    if (warp >= NN) return;
    int start = g_row[warp];
    int d = g_deg_in[warp];
    const float4* hs4 = reinterpret_cast<const float4*>(g_hs);
    float ax = 0.f, ay = 0.f, az = 0.f, aw = 0.f;
    int e = 0;
    for (; e + 2 <= d; e += 2) {
        int s0 = g_csr[start + e];
        int s1 = g_csr[start + e + 1];
        float4 v0 = hs4[(size_t)s0 * 32 + lane];
        float4 v1 = hs4[(size_t)s1 * 32 + lane];
        ax += v0.x + v1.x; ay += v0.y + v1.y;
        az += v0.z + v1.z; aw += v0.w + v1.w;
    }
    if (e < d) {
        int s = g_csr[start + e];
        float4 v = hs4[(size_t)s * 32 + lane];
        ax += v.x; ay += v.y; az += v.z; aw += v.w;
    }
    float rs = rsqrtf((float)(d > 0 ? d : 1));
    float4 bb = reinterpret_cast<const float4*>(bias)[lane];
    float4 r;
    r.x = fmaxf(fmaf(ax, rs, bb.x), 0.f);
    r.y = fmaxf(fmaf(ay, rs, bb.y), 0.f);
    r.z = fmaxf(fmaf(az, rs, bb.z), 0.f);
    r.w = fmaxf(fmaf(aw, rs, bb.w), 0.f);
    reinterpret_cast<float4*>(out)[(size_t)warp * 32 + lane] = r;
}

// ---------------- SumPooling: emb[gid[n], col_off + f] += h2[n, f] (gid sorted -> run-length) ----------------
#define POOL_CHUNK 64
__global__ void pool_kernel(const float* __restrict__ h2, const int* __restrict__ gid,
                            float* __restrict__ emb, int col_off)
{
    int f = threadIdx.x;                       // 0..127
    int n0 = blockIdx.x * POOL_CHUNK;
    int n1 = n0 + POOL_CHUNK; if (n1 > NN) n1 = NN;
    if (n0 >= NN) return;
    float local = 0.f;
    int g = gid[n0];
    for (int n = n0; n < n1; n++) {
        int gn = gid[n];
        if (gn != g) {
            atomicAdd(&emb[(size_t)g * 384 + col_off + f], local);
            local = 0.f;
            g = gn;
        }
        local += h2[(size_t)n * 128 + f];
    }
    atomicAdd(&emb[(size_t)g * 384 + col_off + f], local);
}

// ---------------- Head: BN -> fc1 -> relu -> fc2 -> log_softmax ----------------
__global__ __launch_bounds__(128) void head_kernel(
    const float* __restrict__ emb,
    const float* __restrict__ gamma, const float* __restrict__ beta,
    const float* __restrict__ mean, const float* __restrict__ var,
    const float* __restrict__ fc1W, const float* __restrict__ fc1b,
    const float* __restrict__ fc2W, const float* __restrict__ fc2b,
    float* __restrict__ outlp)
{
    __shared__ float s[384];
    __shared__ float h[128];
    __shared__ float lg[OUTC];
    int b = blockIdx.x;
    int t = threadIdx.x;
    for (int i = t; i < 384; i += 128) {
        float v = emb[(size_t)b * 384 + i];
        s[i] = (v - mean[i]) * rsqrtf(var[i] + EPSBN) * gamma[i] + beta[i];
    }
    __syncthreads();
    float acc = fc1b[t];
    #pragma unroll 4
    for (int k = 0; k < 384; k++) acc = fmaf(s[k], fc1W[(size_t)k * 128 + t], acc);
    h[t] = fmaxf(acc, 0.f);
    __syncthreads();
    if (t < OUTC) {
        float a = fc2b[t];
        #pragma unroll 4
        for (int k = 0; k < 128; k++) a = fmaf(h[k], fc2W[(size_t)k * OUTC + t], a);
        lg[t] = a;
    }
    __syncthreads();
    if (t == 0) {
        float mx = lg[0];
        #pragma unroll
        for (int o = 1; o < OUTC; o++) mx = fmaxf(mx, lg[o]);
        float se = 0.f;
        #pragma unroll
        for (int o = 0; o < OUTC; o++) se += expf(lg[o] - mx);
        float lse = mx + logf(se);
        #pragma unroll
        for (int o = 0; o < OUTC; o++) outlp[(size_t)b * OUTC + o] = lg[o] - lse;
    }
}

// ---------------- launch ----------------
extern "C" void kernel_launch(void* const* d_in, const int* in_sizes, int n_in,
                              void* d_out, int out_size)
{
    const float* x[3];
    const int* src[3];
    const int* dst[3];
    const int* gid[3];

    // Input ordering: dict order (x1,src1,dst1,gid1,...) vs signature order (x1,x2,x3,src1,dst1,...)
    if (in_sizes[1] == EE) {
        for (int g = 0; g < 3; g++) {
            x[g]   = (const float*)d_in[4 * g + 0];
            src[g] = (const int*)  d_in[4 * g + 1];
            dst[g] = (const int*)  d_in[4 * g + 2];
            gid[g] = (const int*)  d_in[4 * g + 3];
        }
    } else {
        for (int g = 0; g < 3; g++) {
            x[g]   = (const float*)d_in[g];
            src[g] = (const int*)  d_in[3 + 2 * g];
            dst[g] = (const int*)  d_in[4 + 2 * g];
            gid[g] = (const int*)  d_in[9 + g];
        }
    }
    const float* W1   = (const float*)d_in[12];
    const float* b1   = (const float*)d_in[13];
    const float* W2   = (const float*)d_in[14];
    const float* b2   = (const float*)d_in[15];
    const float* gma  = (const float*)d_in[16];
    const float* bta  = (const float*)d_in[17];
    const float* mean = (const float*)d_in[18];
    const float* var  = (const float*)d_in[19];
    const float* f1W  = (const float*)d_in[20];
    const float* f1b  = (const float*)d_in[21];
    const float* f2W  = (const float*)d_in[22];
    const float* f2b  = (const float*)d_in[23];

    float* out = (float*)d_out;
    float* emb = out;                    // [256, 384]
    float* lp  = out + (size_t)BB * 384; // [256, 10]

    float* hs_p; float* h1_p; float* h2_p;
    cudaGetSymbolAddress((void**)&hs_p, g_hs);
    cudaGetSymbolAddress((void**)&h1_p, g_h1);
    cudaGetSymbolAddress((void**)&h2_p, g_h2);

    zero_float_kernel<<<(BB * 384 + 255) / 256, 256>>>(emb, BB * 384);

    const int gemm_blocks = (NN + 127) / 128;
    const int spmm_blocks = (NN + 7) / 8;          // 8 warps/block
    const int pool_blocks = (NN + POOL_CHUNK - 1) / POOL_CHUNK;

    for (int g = 0; g < 3; g++) {
        zero_deg_kernel<<<(NN + 255) / 256, 256>>>();
        degree_kernel<<<(EE + 255) / 256, 256>>>(src[g], dst[g]);
        scan_local_kernel<<<NSCAN_BLOCKS, SCAN_BLK>>>();
        scan_bsum_kernel<<<1, 32>>>();
        scan_add_kernel<<<NSCAN_BLOCKS, SCAN_BLK>>>();
        scatter_kernel<<<(EE + 255) / 256, 256>>>(src[g], dst[g]);

        // layer 1
        gemm_scale_kernel<<<gemm_blocks, 256>>>(x[g], W1, hs_p, NN);
        spmm_kernel<<<spmm_blocks, 256>>>(b1, h1_p);
        // layer 2
        gemm_scale_kernel<<<gemm_blocks, 256>>>(h1_p, W2, hs_p, NN);
        spmm_kernel<<<spmm_blocks, 256>>>(b2, h2_p);

        pool_kernel<<<pool_blocks, 128>>>(h2_p, gid[g], emb, g * 128);
    }

    head_kernel<<<BB, 128>>>(emb, gma, bta, mean, var, f1W, f1b, f2W, f2b, lp);
}

// round 3
// speedup vs baseline: 1.8104x; 1.2894x over previous
#include <cuda_runtime.h>
#include <cstdint>

#define NN 50000
#define EE 800000
#define BB 256
#define FEAT 128
#define OUTC 10
#define EPSBN 1e-5f
#define SCAN_BLK 1024
#define NSCAN_BLOCKS ((NN + SCAN_BLK - 1) / SCAN_BLK)   // 49

// ---------------- static scratch (device globals; no allocation) ----------------
__device__ float g_hs[NN * FEAT];   // GEMM output, pre-scaled by dout^-1/2 (gather source)
__device__ float g_h1[NN * FEAT];   // layer-1 output
__device__ float g_h2[NN * FEAT];   // layer-2 output
__device__ int g_deg_out[NN];
__device__ int g_deg_in[NN];
__device__ int g_row[NN];           // CSR row start (by dst)
__device__ int g_cur[NN];           // scatter cursors
__device__ int g_csr[EE];           // src ids sorted by dst
__device__ int g_bsum[NSCAN_BLOCKS];

// ---------------- small utility kernels ----------------
__global__ void zero_float_kernel(float* p, int n) {
    int i = blockIdx.x * blockDim.x + threadIdx.x;
    if (i < n) p[i] = 0.0f;
}

__global__ void zero_deg_kernel() {
    int i = blockIdx.x * blockDim.x + threadIdx.x;
    if (i < NN) { g_deg_out[i] = 0; g_deg_in[i] = 0; }
}

__global__ void degree_kernel(const int* __restrict__ src, const int* __restrict__ dst) {
    int i = blockIdx.x * blockDim.x + threadIdx.x;
    if (i < EE) {
        atomicAdd(&g_deg_out[src[i]], 1);
        atomicAdd(&g_deg_in[dst[i]], 1);
    }
}

// ---- multi-block exclusive scan of g_deg_in -> g_row ----
__global__ __launch_bounds__(SCAN_BLK) void scan_local_kernel() {
    __shared__ int sm[SCAN_BLK];
    int t = threadIdx.x;
    int idx = blockIdx.x * SCAN_BLK + t;
    int v = (idx < NN) ? g_deg_in[idx] : 0;
    sm[t] = v;
    __syncthreads();
    #pragma unroll
    for (int off = 1; off < SCAN_BLK; off <<= 1) {
        int y = (t >= off) ? sm[t - off] : 0;
        __syncthreads();
        sm[t] += y;
        __syncthreads();
    }
    if (idx < NN) g_row[idx] = sm[t] - v;     // local exclusive
    if (t == SCAN_BLK - 1) g_bsum[blockIdx.x] = sm[t];
}

__global__ void scan_bsum_kernel() {
    if (threadIdx.x == 0) {
        int run = 0;
        #pragma unroll 1
        for (int i = 0; i < NSCAN_BLOCKS; i++) {
            int tmp = g_bsum[i];
            g_bsum[i] = run;
            run += tmp;
        }
    }
}

__global__ __launch_bounds__(SCAN_BLK) void scan_add_kernel() {
    int idx = blockIdx.x * SCAN_BLK + threadIdx.x;
    if (idx < NN) {
        g_row[idx] += g_bsum[blockIdx.x];
        g_cur[idx] = 0;
    }
}

__global__ void scatter_kernel(const int* __restrict__ src, const int* __restrict__ dst) {
    int i = blockIdx.x * blockDim.x + threadIdx.x;
    if (i < EE) {
        int d = dst[i];
        int pos = g_row[d] + atomicAdd(&g_cur[d], 1);
        g_csr[pos] = src[i];
    }
}

// ---------------- tf32 tensor-core GEMM ----------------
// out[m,:] = (A[m,:] @ W) * rsqrt(max(deg_out[m],1))
// A: [nrows,128] row-major, W: [128,128] row-major.
// CTA: 128x128, 8 warps, warp tile 32x64, mma.sync m16n8k8 tf32.
#define A_STRIDE 36
#define W_STRIDE 136

__device__ __forceinline__ uint32_t f2tf32(float f) {
    uint32_t u;
    asm("cvt.rna.tf32.f32 %0, %1;" : "=r"(u) : "f"(f));
    return u;
}

__device__ __forceinline__ void mma_tf32(float c[4],
                                         uint32_t a0, uint32_t a1, uint32_t a2, uint32_t a3,
                                         uint32_t b0, uint32_t b1) {
    asm volatile(
        "mma.sync.aligned.m16n8k8.row.col.f32.tf32.tf32.f32 "
        "{%0,%1,%2,%3}, {%4,%5,%6,%7}, {%8,%9}, {%0,%1,%2,%3};\n"
        : "+f"(c[0]), "+f"(c[1]), "+f"(c[2]), "+f"(c[3])
        : "r"(a0), "r"(a1), "r"(a2), "r"(a3), "r"(b0), "r"(b1));
}

__global__ __launch_bounds__(256) void gemm_tc_kernel(
    const float* __restrict__ A, const float* __restrict__ W,
    float* __restrict__ out, int nrows)
{
    __shared__ uint32_t As[128 * A_STRIDE];   // [m][k], stride 36 (banks: 4g+tig distinct)
    __shared__ uint32_t Ws[32 * W_STRIDE];    // [k][n], stride 136 (banks: 8tig+g distinct)

    int tid = threadIdx.x;
    int warp = tid >> 5;
    int lane = tid & 31;
    int g = lane >> 2;       // 0..7
    int tig = lane & 3;      // 0..3
    int warp_m = (warp >> 1) * 32;   // 0,32,64,96
    int warp_n = (warp & 1) * 64;    // 0,64
    int row0 = blockIdx.x * 128;

    float acc[2][8][4];
    #pragma unroll
    for (int mi = 0; mi < 2; mi++)
        #pragma unroll
        for (int ni = 0; ni < 8; ni++)
            #pragma unroll
            for (int q = 0; q < 4; q++) acc[mi][ni][q] = 0.0f;

    for (int k0 = 0; k0 < 128; k0 += 32) {
        // load A tile [128 x 32] -> As (convert to tf32)
        #pragma unroll
        for (int rep = 0; rep < 4; rep++) {
            int idx = tid + rep * 256;          // 0..1023
            int am = idx >> 3;                  // 0..127
            int ak = (idx & 7) * 4;             // 0..28
            int gr = row0 + am;
            float4 av = make_float4(0.f, 0.f, 0.f, 0.f);
            if (gr < nrows) av = *reinterpret_cast<const float4*>(A + (size_t)gr * 128 + k0 + ak);
            uint4 tv;
            tv.x = f2tf32(av.x); tv.y = f2tf32(av.y);
            tv.z = f2tf32(av.z); tv.w = f2tf32(av.w);
            *reinterpret_cast<uint4*>(&As[am * A_STRIDE + ak]) = tv;
        }
        // load W tile [32 x 128] -> Ws
        #pragma unroll
        for (int rep = 0; rep < 4; rep++) {
            int idx = tid + rep * 256;
            int bk = idx >> 5;                  // 0..31
            int bn = (idx & 31) * 4;            // 0..124
            float4 wv = *reinterpret_cast<const float4*>(W + (size_t)(k0 + bk) * 128 + bn);
            uint4 tv;
            tv.x = f2tf32(wv.x); tv.y = f2tf32(wv.y);
            tv.z = f2tf32(wv.z); tv.w = f2tf32(wv.w);
            *reinterpret_cast<uint4*>(&Ws[bk * W_STRIDE + bn]) = tv;
        }
        __syncthreads();

        #pragma unroll
        for (int ks = 0; ks < 4; ks++) {
            int kk = ks * 8;
            uint32_t af[2][4];
            #pragma unroll
            for (int mi = 0; mi < 2; mi++) {
                int r = warp_m + mi * 16 + g;
                af[mi][0] = As[r * A_STRIDE + kk + tig];
                af[mi][1] = As[(r + 8) * A_STRIDE + kk + tig];
                af[mi][2] = As[r * A_STRIDE + kk + tig + 4];
                af[mi][3] = As[(r + 8) * A_STRIDE + kk + tig + 4];
            }
            #pragma unroll
            for (int ni = 0; ni < 8; ni++) {
                int nc = warp_n + ni * 8 + g;
                uint32_t b0 = Ws[(kk + tig) * W_STRIDE + nc];
                uint32_t b1 = Ws[(kk + tig + 4) * W_STRIDE + nc];
                mma_tf32(acc[0][ni], af[0][0], af[0][1], af[0][2], af[0][3], b0, b1);
                mma_tf32(acc[1][ni], af[1][0], af[1][1], af[1][2], af[1][3], b0, b1);
            }
        }
        __syncthreads();
    }

    // epilogue: scale rows by rsqrt(deg_out) and store
    #pragma unroll
    for (int mi = 0; mi < 2; mi++) {
        int r0 = row0 + warp_m + mi * 16 + g;
        int r1 = r0 + 8;
        float rs0 = 1.f, rs1 = 1.f;
        if (r0 < nrows) { int d = g_deg_out[r0]; rs0 = rsqrtf((float)(d > 0 ? d : 1)); }
        if (r1 < nrows) { int d = g_deg_out[r1]; rs1 = rsqrtf((float)(d > 0 ? d : 1)); }
        #pragma unroll
        for (int ni = 0; ni < 8; ni++) {
            int col = warp_n + ni * 8 + tig * 2;
            if (r0 < nrows) {
                float2 v; v.x = acc[mi][ni][0] * rs0; v.y = acc[mi][ni][1] * rs0;
                *reinterpret_cast<float2*>(out + (size_t)r0 * 128 + col) = v;
            }
            if (r1 < nrows) {
                float2 v; v.x = acc[mi][ni][2] * rs1; v.y = acc[mi][ni][3] * rs1;
                *reinterpret_cast<float2*>(out + (size_t)r1 * 128 + col) = v;
            }
        }
    }
}

// ---------------- SpMM gather: out[i] = relu((sum_{e in csr[i]} hs[src_e]) * din^-1/2 + b) ----------------
__global__ __launch_bounds__(256) void spmm_kernel(const float* __restrict__ bias,
                                                   float* __restrict__ out)
{
    int warp = (blockIdx.x * blockDim.x + threadIdx.x) >> 5;
    int lane = threadIdx.x & 31;
    if (warp >= NN) return;
    int start = g_row[warp];
    int d = g_deg_in[warp];
    const float4* hs4 = reinterpret_cast<const float4*>(g_hs);
    float ax = 0.f, ay = 0.f, az = 0.f, aw = 0.f;
    int e = 0;
    for (; e + 4 <= d; e += 4) {
        int s0 = g_csr[start + e];
        int s1 = g_csr[start + e + 1];
        int s2 = g_csr[start + e + 2];
        int s3 = g_csr[start + e + 3];
        float4 v0 = hs4[(size_t)s0 * 32 + lane];
        float4 v1 = hs4[(size_t)s1 * 32 + lane];
        float4 v2 = hs4[(size_t)s2 * 32 + lane];
        float4 v3 = hs4[(size_t)s3 * 32 + lane];
        ax += (v0.x + v1.x) + (v2.x + v3.x);
        ay += (v0.y + v1.y) + (v2.y + v3.y);
        az += (v0.z + v1.z) + (v2.z + v3.z);
        aw += (v0.w + v1.w) + (v2.w + v3.w);
    }
    for (; e < d; e++) {
        int s = g_csr[start + e];
        float4 v = hs4[(size_t)s * 32 + lane];
        ax += v.x; ay += v.y; az += v.z; aw += v.w;
    }
    float rs = rsqrtf((float)(d > 0 ? d : 1));
    float4 bb = reinterpret_cast<const float4*>(bias)[lane];
    float4 r;
    r.x = fmaxf(fmaf(ax, rs, bb.x), 0.f);
    r.y = fmaxf(fmaf(ay, rs, bb.y), 0.f);
    r.z = fmaxf(fmaf(az, rs, bb.z), 0.f);
    r.w = fmaxf(fmaf(aw, rs, bb.w), 0.f);
    reinterpret_cast<float4*>(out)[(size_t)warp * 32 + lane] = r;
}

// ---------------- SumPooling ----------------
#define POOL_CHUNK 64
__global__ void pool_kernel(const float* __restrict__ h2, const int* __restrict__ gid,
                            float* __restrict__ emb, int col_off)
{
    int f = threadIdx.x;                       // 0..127
    int n0 = blockIdx.x * POOL_CHUNK;
    int n1 = n0 + POOL_CHUNK; if (n1 > NN) n1 = NN;
    if (n0 >= NN) return;
    float local = 0.f;
    int g = gid[n0];
    for (int n = n0; n < n1; n++) {
        int gn = gid[n];
        if (gn != g) {
            atomicAdd(&emb[(size_t)g * 384 + col_off + f], local);
            local = 0.f;
            g = gn;
        }
        local += h2[(size_t)n * 128 + f];
    }
    atomicAdd(&emb[(size_t)g * 384 + col_off + f], local);
}

// ---------------- Head: BN -> fc1 -> relu -> fc2 -> log_softmax ----------------
__global__ __launch_bounds__(128) void head_kernel(
    const float* __restrict__ emb,
    const float* __restrict__ gamma, const float* __restrict__ beta,
    const float* __restrict__ mean, const float* __restrict__ var,
    const float* __restrict__ fc1W, const float* __restrict__ fc1b,
    const float* __restrict__ fc2W, const float* __restrict__ fc2b,
    float* __restrict__ outlp)
{
    __shared__ float s[384];
    __shared__ float h[128];
    __shared__ float lg[OUTC];
    int b = blockIdx.x;
    int t = threadIdx.x;
    for (int i = t; i < 384; i += 128) {
        float v = emb[(size_t)b * 384 + i];
        s[i] = (v - mean[i]) * rsqrtf(var[i] + EPSBN) * gamma[i] + beta[i];
    }
    __syncthreads();
    float acc = fc1b[t];
    #pragma unroll 4
    for (int k = 0; k < 384; k++) acc = fmaf(s[k], fc1W[(size_t)k * 128 + t], acc);
    h[t] = fmaxf(acc, 0.f);
    __syncthreads();
    if (t < OUTC) {
        float a = fc2b[t];
        #pragma unroll 4
        for (int k = 0; k < 128; k++) a = fmaf(h[k], fc2W[(size_t)k * OUTC + t], a);
        lg[t] = a;
    }
    __syncthreads();
    if (t == 0) {
        float mx = lg[0];
        #pragma unroll
        for (int o = 1; o < OUTC; o++) mx = fmaxf(mx, lg[o]);
        float se = 0.f;
        #pragma unroll
        for (int o = 0; o < OUTC; o++) se += expf(lg[o] - mx);
        float lse = mx + logf(se);
        #pragma unroll
        for (int o = 0; o < OUTC; o++) outlp[(size_t)b * OUTC + o] = lg[o] - lse;
    }
}

// ---------------- launch ----------------
extern "C" void kernel_launch(void* const* d_in, const int* in_sizes, int n_in,
                              void* d_out, int out_size)
{
    const float* x[3];
    const int* src[3];
    const int* dst[3];
    const int* gid[3];

    if (in_sizes[1] == EE) {
        for (int g = 0; g < 3; g++) {
            x[g]   = (const float*)d_in[4 * g + 0];
            src[g] = (const int*)  d_in[4 * g + 1];
            dst[g] = (const int*)  d_in[4 * g + 2];
            gid[g] = (const int*)  d_in[4 * g + 3];
        }
    } else {
        for (int g = 0; g < 3; g++) {
            x[g]   = (const float*)d_in[g];
            src[g] = (const int*)  d_in[3 + 2 * g];
            dst[g] = (const int*)  d_in[4 + 2 * g];
            gid[g] = (const int*)  d_in[9 + g];
        }
    }
    const float* W1   = (const float*)d_in[12];
    const float* b1   = (const float*)d_in[13];
    const float* W2   = (const float*)d_in[14];
    const float* b2   = (const float*)d_in[15];
    const float* gma  = (const float*)d_in[16];
    const float* bta  = (const float*)d_in[17];
    const float* mean = (const float*)d_in[18];
    const float* var  = (const float*)d_in[19];
    const float* f1W  = (const float*)d_in[20];
    const float* f1b  = (const float*)d_in[21];
    const float* f2W  = (const float*)d_in[22];
    const float* f2b  = (const float*)d_in[23];

    float* out = (float*)d_out;
    float* emb = out;                    // [256, 384]
    float* lp  = out + (size_t)BB * 384; // [256, 10]

    float* hs_p; float* h1_p; float* h2_p;
    cudaGetSymbolAddress((void**)&hs_p, g_hs);
    cudaGetSymbolAddress((void**)&h1_p, g_h1);
    cudaGetSymbolAddress((void**)&h2_p, g_h2);

    zero_float_kernel<<<(BB * 384 + 255) / 256, 256>>>(emb, BB * 384);

    const int gemm_blocks = (NN + 127) / 128;      // 391
    const int spmm_blocks = (NN + 7) / 8;          // 8 warps/block
    const int pool_blocks = (NN + POOL_CHUNK - 1) / POOL_CHUNK;

    for (int g = 0; g < 3; g++) {
        zero_deg_kernel<<<(NN + 255) / 256, 256>>>();
        degree_kernel<<<(EE + 255) / 256, 256>>>(src[g], dst[g]);
        scan_local_kernel<<<NSCAN_BLOCKS, SCAN_BLK>>>();
        scan_bsum_kernel<<<1, 32>>>();
        scan_add_kernel<<<NSCAN_BLOCKS, SCAN_BLK>>>();
        scatter_kernel<<<(EE + 255) / 256, 256>>>(src[g], dst[g]);

        // layer 1
        gemm_tc_kernel<<<gemm_blocks, 256>>>(x[g], W1, hs_p, NN);
        spmm_kernel<<<spmm_blocks, 256>>>(b1, h1_p);
        // layer 2
        gemm_tc_kernel<<<gemm_blocks, 256>>>(h1_p, W2, hs_p, NN);
        spmm_kernel<<<spmm_blocks, 256>>>(b2, h2_p);

        pool_kernel<<<pool_blocks, 128>>>(h2_p, gid[g], emb, g * 128);
    }

    head_kernel<<<BB, 128>>>(emb, gma, bta, mean, var, f1W, f1b, f2W, f2b, lp);
}

// round 4
// speedup vs baseline: 2.1318x; 1.1776x over previous
#include <cuda_runtime.h>
#include <cuda_fp16.h>
#include <cstdint>

#define NN 50000
#define EE 800000
#define BB 256
#define FEAT 128
#define OUTC 10
#define EPSBN 1e-5f
#define SCAN_BLK 1024
#define NSCAN_BLOCKS ((NN + SCAN_BLK - 1) / SCAN_BLK)   // 49
#define EDGE_BLOCKS ((EE + 255) / 256)                  // 3125

// ---------------- static scratch (device globals; no allocation) ----------------
__device__ __half g_hs[NN * FEAT];          // GEMM output (deg-scaled), fp16 gather source
__device__ float g_h1[NN * FEAT];           // layer-1 output
__device__ float g_h2[NN * FEAT];           // layer-2 output
__device__ int g_deg_out[3 * NN];
__device__ int g_deg_in[3 * NN];
__device__ int g_row[3 * NN];               // CSR row start (per-graph local)
__device__ int g_cur[3 * NN];               // scatter cursors
__device__ int g_csr[3 * EE];               // src ids sorted by dst, per graph
__device__ int g_bsum[3 * NSCAN_BLOCKS];

// ---------------- batched CSR build ----------------
__global__ void degree_all_kernel(const int* __restrict__ s0, const int* __restrict__ d0,
                                  const int* __restrict__ s1, const int* __restrict__ d1,
                                  const int* __restrict__ s2, const int* __restrict__ d2)
{
    int g = blockIdx.x / EDGE_BLOCKS;
    int e = (blockIdx.x % EDGE_BLOCKS) * 256 + threadIdx.x;
    if (e >= EE) return;
    const int* src = (g == 0) ? s0 : (g == 1) ? s1 : s2;
    const int* dst = (g == 0) ? d0 : (g == 1) ? d1 : d2;
    int off = g * NN;
    atomicAdd(&g_deg_out[off + src[e]], 1);
    atomicAdd(&g_deg_in[off + dst[e]], 1);
}

// per-block local inclusive scan of deg_in -> row (local exclusive), block totals -> bsum
__global__ __launch_bounds__(SCAN_BLK) void scan_local_all_kernel() {
    __shared__ int sm[SCAN_BLK];
    int b = blockIdx.x;
    int g = b / NSCAN_BLOCKS;
    int lb = b % NSCAN_BLOCKS;
    int t = threadIdx.x;
    int li = lb * SCAN_BLK + t;
    int idx = g * NN + li;
    int v = (li < NN) ? g_deg_in[idx] : 0;
    sm[t] = v;
    __syncthreads();
    #pragma unroll
    for (int off = 1; off < SCAN_BLK; off <<= 1) {
        int y = (t >= off) ? sm[t - off] : 0;
        __syncthreads();
        sm[t] += y;
        __syncthreads();
    }
    if (li < NN) g_row[idx] = sm[t] - v;
    if (t == SCAN_BLK - 1) g_bsum[b] = sm[t];
}

// add per-graph prefix of block sums; zero cursors
__global__ __launch_bounds__(SCAN_BLK) void scan_add_all_kernel() {
    __shared__ int s_off;
    int b = blockIdx.x;
    int g = b / NSCAN_BLOCKS;
    int lb = b % NSCAN_BLOCKS;
    int t = threadIdx.x;
    if (t == 0) {
        int run = 0;
        for (int i = 0; i < lb; i++) run += g_bsum[g * NSCAN_BLOCKS + i];
        s_off = run;
    }
    __syncthreads();
    int li = lb * SCAN_BLK + t;
    if (li < NN) {
        int idx = g * NN + li;
        g_row[idx] += s_off;
        g_cur[idx] = 0;
    }
}

__global__ void scatter_all_kernel(const int* __restrict__ s0, const int* __restrict__ d0,
                                   const int* __restrict__ s1, const int* __restrict__ d1,
                                   const int* __restrict__ s2, const int* __restrict__ d2)
{
    int g = blockIdx.x / EDGE_BLOCKS;
    int e = (blockIdx.x % EDGE_BLOCKS) * 256 + threadIdx.x;
    if (e >= EE) return;
    const int* src = (g == 0) ? s0 : (g == 1) ? s1 : s2;
    const int* dst = (g == 0) ? d0 : (g == 1) ? d1 : d2;
    int off = g * NN;
    int d = dst[e];
    int pos = g_row[off + d] + atomicAdd(&g_cur[off + d], 1);
    g_csr[g * EE + pos] = src[e];
}

// ---------------- tf32 tensor-core GEMM, fp16 output ----------------
// out_h[m,:] = half((A[m,:] @ W) * rsqrt(max(deg_out[goff+m],1)))
#define A_STRIDE 36
#define W_STRIDE 136

__device__ __forceinline__ uint32_t f2tf32(float f) {
    uint32_t u;
    asm("cvt.rna.tf32.f32 %0, %1;" : "=r"(u) : "f"(f));
    return u;
}

__device__ __forceinline__ void mma_tf32(float c[4],
                                         uint32_t a0, uint32_t a1, uint32_t a2, uint32_t a3,
                                         uint32_t b0, uint32_t b1) {
    asm volatile(
        "mma.sync.aligned.m16n8k8.row.col.f32.tf32.tf32.f32 "
        "{%0,%1,%2,%3}, {%4,%5,%6,%7}, {%8,%9}, {%0,%1,%2,%3};\n"
        : "+f"(c[0]), "+f"(c[1]), "+f"(c[2]), "+f"(c[3])
        : "r"(a0), "r"(a1), "r"(a2), "r"(a3), "r"(b0), "r"(b1));
}

__global__ __launch_bounds__(256) void gemm_tc_kernel(
    const float* __restrict__ A, const float* __restrict__ W,
    __half* __restrict__ out, int nrows, int goff)
{
    __shared__ uint32_t As[128 * A_STRIDE];
    __shared__ uint32_t Ws[32 * W_STRIDE];

    int tid = threadIdx.x;
    int warp = tid >> 5;
    int lane = tid & 31;
    int g = lane >> 2;
    int tig = lane & 3;
    int warp_m = (warp >> 1) * 32;
    int warp_n = (warp & 1) * 64;
    int row0 = blockIdx.x * 128;

    float acc[2][8][4];
    #pragma unroll
    for (int mi = 0; mi < 2; mi++)
        #pragma unroll
        for (int ni = 0; ni < 8; ni++)
            #pragma unroll
            for (int q = 0; q < 4; q++) acc[mi][ni][q] = 0.0f;

    for (int k0 = 0; k0 < 128; k0 += 32) {
        #pragma unroll
        for (int rep = 0; rep < 4; rep++) {
            int idx = tid + rep * 256;
            int am = idx >> 3;
            int ak = (idx & 7) * 4;
            int gr = row0 + am;
            float4 av = make_float4(0.f, 0.f, 0.f, 0.f);
            if (gr < nrows) av = *reinterpret_cast<const float4*>(A + (size_t)gr * 128 + k0 + ak);
            uint4 tv;
            tv.x = f2tf32(av.x); tv.y = f2tf32(av.y);
            tv.z = f2tf32(av.z); tv.w = f2tf32(av.w);
            *reinterpret_cast<uint4*>(&As[am * A_STRIDE + ak]) = tv;
        }
        #pragma unroll
        for (int rep = 0; rep < 4; rep++) {
            int idx = tid + rep * 256;
            int bk = idx >> 5;
            int bn = (idx & 31) * 4;
            float4 wv = *reinterpret_cast<const float4*>(W + (size_t)(k0 + bk) * 128 + bn);
            uint4 tv;
            tv.x = f2tf32(wv.x); tv.y = f2tf32(wv.y);
            tv.z = f2tf32(wv.z); tv.w = f2tf32(wv.w);
            *reinterpret_cast<uint4*>(&Ws[bk * W_STRIDE + bn]) = tv;
        }
        __syncthreads();

        #pragma unroll
        for (int ks = 0; ks < 4; ks++) {
            int kk = ks * 8;
            uint32_t af[2][4];
            #pragma unroll
            for (int mi = 0; mi < 2; mi++) {
                int r = warp_m + mi * 16 + g;
                af[mi][0] = As[r * A_STRIDE + kk + tig];
                af[mi][1] = As[(r + 8) * A_STRIDE + kk + tig];
                af[mi][2] = As[r * A_STRIDE + kk + tig + 4];
                af[mi][3] = As[(r + 8) * A_STRIDE + kk + tig + 4];
            }
            #pragma unroll
            for (int ni = 0; ni < 8; ni++) {
                int nc = warp_n + ni * 8 + g;
                uint32_t b0 = Ws[(kk + tig) * W_STRIDE + nc];
                uint32_t b1 = Ws[(kk + tig + 4) * W_STRIDE + nc];
                mma_tf32(acc[0][ni], af[0][0], af[0][1], af[0][2], af[0][3], b0, b1);
                mma_tf32(acc[1][ni], af[1][0], af[1][1], af[1][2], af[1][3], b0, b1);
            }
        }
        __syncthreads();
    }

    #pragma unroll
    for (int mi = 0; mi < 2; mi++) {
        int r0 = row0 + warp_m + mi * 16 + g;
        int r1 = r0 + 8;
        float rs0 = 1.f, rs1 = 1.f;
        if (r0 < nrows) { int d = g_deg_out[goff + r0]; rs0 = rsqrtf((float)(d > 0 ? d : 1)); }
        if (r1 < nrows) { int d = g_deg_out[goff + r1]; rs1 = rsqrtf((float)(d > 0 ? d : 1)); }
        #pragma unroll
        for (int ni = 0; ni < 8; ni++) {
            int col = warp_n + ni * 8 + tig * 2;
            if (r0 < nrows) {
                __half2 v = __floats2half2_rn(acc[mi][ni][0] * rs0, acc[mi][ni][1] * rs0);
                *reinterpret_cast<__half2*>(out + (size_t)r0 * 128 + col) = v;
            }
            if (r1 < nrows) {
                __half2 v = __floats2half2_rn(acc[mi][ni][2] * rs1, acc[mi][ni][3] * rs1);
                *reinterpret_cast<__half2*>(out + (size_t)r1 * 128 + col) = v;
            }
        }
    }
}

// ---------------- SpMM gather (fp16 source, fp32 accum) ----------------
// out[i] = relu((sum_{e in csr[i]} hs[src_e]) * din^-1/2 + b)
// one warp per dst node; lane covers 4 feats (uint2 = 4 halves = 8B; 32*8=256B/row)
__global__ __launch_bounds__(256) void spmm_kernel(const float* __restrict__ bias,
                                                   float* __restrict__ out, int goff, int coff)
{
    int node = (blockIdx.x * blockDim.x + threadIdx.x) >> 5;
    int lane = threadIdx.x & 31;
    if (node >= NN) return;
    int start = g_row[goff + node];
    int d = g_deg_in[goff + node];
    const int* csr = g_csr + coff;
    const uint2* hs8 = reinterpret_cast<const uint2*>(g_hs);   // 4 halves per uint2
    float ax = 0.f, ay = 0.f, az = 0.f, aw = 0.f;
    int e = 0;
    for (; e + 4 <= d; e += 4) {
        int s0 = csr[start + e];
        int s1 = csr[start + e + 1];
        int s2 = csr[start + e + 2];
        int s3 = csr[start + e + 3];
        uint2 u0 = hs8[(size_t)s0 * 32 + lane];
        uint2 u1 = hs8[(size_t)s1 * 32 + lane];
        uint2 u2 = hs8[(size_t)s2 * 32 + lane];
        uint2 u3 = hs8[(size_t)s3 * 32 + lane];
        float2 a0 = __half22float2(*reinterpret_cast<__half2*>(&u0.x));
        float2 b0 = __half22float2(*reinterpret_cast<__half2*>(&u0.y));
        float2 a1 = __half22float2(*reinterpret_cast<__half2*>(&u1.x));
        float2 b1 = __half22float2(*reinterpret_cast<__half2*>(&u1.y));
        float2 a2 = __half22float2(*reinterpret_cast<__half2*>(&u2.x));
        float2 b2 = __half22float2(*reinterpret_cast<__half2*>(&u2.y));
        float2 a3 = __half22float2(*reinterpret_cast<__half2*>(&u3.x));
        float2 b3 = __half22float2(*reinterpret_cast<__half2*>(&u3.y));
        ax += (a0.x + a1.x) + (a2.x + a3.x);
        ay += (a0.y + a1.y) + (a2.y + a3.y);
        az += (b0.x + b1.x) + (b2.x + b3.x);
        aw += (b0.y + b1.y) + (b2.y + b3.y);
    }
    for (; e < d; e++) {
        int s = csr[start + e];
        uint2 u = hs8[(size_t)s * 32 + lane];
        float2 a = __half22float2(*reinterpret_cast<__half2*>(&u.x));
        float2 b = __half22float2(*reinterpret_cast<__half2*>(&u.y));
        ax += a.x; ay += a.y; az += b.x; aw += b.y;
    }
    float rs = rsqrtf((float)(d > 0 ? d : 1));
    float4 bb = reinterpret_cast<const float4*>(bias)[lane];
    float4 r;
    r.x = fmaxf(fmaf(ax, rs, bb.x), 0.f);
    r.y = fmaxf(fmaf(ay, rs, bb.y), 0.f);
    r.z = fmaxf(fmaf(az, rs, bb.z), 0.f);
    r.w = fmaxf(fmaf(aw, rs, bb.w), 0.f);
    reinterpret_cast<float4*>(out)[(size_t)node * 32 + lane] = r;
}

// ---------------- SumPooling ----------------
#define POOL_CHUNK 64
__global__ void pool_kernel(const float* __restrict__ h2, const int* __restrict__ gid,
                            float* __restrict__ emb, int col_off)
{
    int f = threadIdx.x;
    int n0 = blockIdx.x * POOL_CHUNK;
    int n1 = n0 + POOL_CHUNK; if (n1 > NN) n1 = NN;
    if (n0 >= NN) return;
    float local = 0.f;
    int g = gid[n0];
    for (int n = n0; n < n1; n++) {
        int gn = gid[n];
        if (gn != g) {
            atomicAdd(&emb[(size_t)g * 384 + col_off + f], local);
            local = 0.f;
            g = gn;
        }
        local += h2[(size_t)n * 128 + f];
    }
    atomicAdd(&emb[(size_t)g * 384 + col_off + f], local);
}

// ---------------- Head: BN -> fc1 -> relu -> fc2 -> log_softmax ----------------
__global__ __launch_bounds__(128) void head_kernel(
    const float* __restrict__ emb,
    const float* __restrict__ gamma, const float* __restrict__ beta,
    const float* __restrict__ mean, const float* __restrict__ var,
    const float* __restrict__ fc1W, const float* __restrict__ fc1b,
    const float* __restrict__ fc2W, const float* __restrict__ fc2b,
    float* __restrict__ outlp)
{
    __shared__ float s[384];
    __shared__ float h[128];
    __shared__ float lg[OUTC];
    int b = blockIdx.x;
    int t = threadIdx.x;
    for (int i = t; i < 384; i += 128) {
        float v = emb[(size_t)b * 384 + i];
        s[i] = (v - mean[i]) * rsqrtf(var[i] + EPSBN) * gamma[i] + beta[i];
    }
    __syncthreads();
    float acc = fc1b[t];
    #pragma unroll 4
    for (int k = 0; k < 384; k++) acc = fmaf(s[k], fc1W[(size_t)k * 128 + t], acc);
    h[t] = fmaxf(acc, 0.f);
    __syncthreads();
    if (t < OUTC) {
        float a = fc2b[t];
        #pragma unroll 4
        for (int k = 0; k < 128; k++) a = fmaf(h[k], fc2W[(size_t)k * OUTC + t], a);
        lg[t] = a;
    }
    __syncthreads();
    if (t == 0) {
        float mx = lg[0];
        #pragma unroll
        for (int o = 1; o < OUTC; o++) mx = fmaxf(mx, lg[o]);
        float se = 0.f;
        #pragma unroll
        for (int o = 0; o < OUTC; o++) se += expf(lg[o] - mx);
        float lse = mx + logf(se);
        #pragma unroll
        for (int o = 0; o < OUTC; o++) outlp[(size_t)b * OUTC + o] = lg[o] - lse;
    }
}

// ---------------- launch ----------------
extern "C" void kernel_launch(void* const* d_in, const int* in_sizes, int n_in,
                              void* d_out, int out_size)
{
    const float* x[3];
    const int* src[3];
    const int* dst[3];
    const int* gid[3];

    if (in_sizes[1] == EE) {
        for (int g = 0; g < 3; g++) {
            x[g]   = (const float*)d_in[4 * g + 0];
            src[g] = (const int*)  d_in[4 * g + 1];
            dst[g] = (const int*)  d_in[4 * g + 2];
            gid[g] = (const int*)  d_in[4 * g + 3];
        }
    } else {
        for (int g = 0; g < 3; g++) {
            x[g]   = (const float*)d_in[g];
            src[g] = (const int*)  d_in[3 + 2 * g];
            dst[g] = (const int*)  d_in[4 + 2 * g];
            gid[g] = (const int*)  d_in[9 + g];
        }
    }
    const float* W1   = (const float*)d_in[12];
    const float* b1   = (const float*)d_in[13];
    const float* W2   = (const float*)d_in[14];
    const float* b2   = (const float*)d_in[15];
    const float* gma  = (const float*)d_in[16];
    const float* bta  = (const float*)d_in[17];
    const float* mean = (const float*)d_in[18];
    const float* var  = (const float*)d_in[19];
    const float* f1W  = (const float*)d_in[20];
    const float* f1b  = (const float*)d_in[21];
    const float* f2W  = (const float*)d_in[22];
    const float* f2b  = (const float*)d_in[23];

    float* out = (float*)d_out;
    float* emb = out;                    // [256, 384]
    float* lp  = out + (size_t)BB * 384; // [256, 10]

    __half* hs_p; float* h1_p; float* h2_p;
    void* dego_p; void* degi_p;
    cudaGetSymbolAddress((void**)&hs_p, g_hs);
    cudaGetSymbolAddress((void**)&h1_p, g_h1);
    cudaGetSymbolAddress((void**)&h2_p, g_h2);
    cudaGetSymbolAddress(&dego_p, g_deg_out);
    cudaGetSymbolAddress(&degi_p, g_deg_in);

    // zero deg arrays + emb via async memsets (capturable)
    cudaMemsetAsync(dego_p, 0, 3 * NN * sizeof(int));
    cudaMemsetAsync(degi_p, 0, 3 * NN * sizeof(int));
    cudaMemsetAsync(emb, 0, BB * 384 * sizeof(float));

    // batched CSR build for all 3 graphs
    degree_all_kernel<<<3 * EDGE_BLOCKS, 256>>>(src[0], dst[0], src[1], dst[1], src[2], dst[2]);
    scan_local_all_kernel<<<3 * NSCAN_BLOCKS, SCAN_BLK>>>();
    scan_add_all_kernel<<<3 * NSCAN_BLOCKS, SCAN_BLK>>>();
    scatter_all_kernel<<<3 * EDGE_BLOCKS, 256>>>(src[0], dst[0], src[1], dst[1], src[2], dst[2]);

    const int gemm_blocks = (NN + 127) / 128;      // 391
    const int spmm_blocks = (NN + 7) / 8;          // 8 warps/block
    const int pool_blocks = (NN + POOL_CHUNK - 1) / POOL_CHUNK;

    for (int g = 0; g < 3; g++) {
        int goff = g * NN;
        int coff = g * EE;
        // layer 1
        gemm_tc_kernel<<<gemm_blocks, 256>>>(x[g], W1, hs_p, NN, goff);
        spmm_kernel<<<spmm_blocks, 256>>>(b1, h1_p, goff, coff);
        // layer 2
        gemm_tc_kernel<<<gemm_blocks, 256>>>(h1_p, W2, hs_p, NN, goff);
        spmm_kernel<<<spmm_blocks, 256>>>(b2, h2_p, goff, coff);

        pool_kernel<<<pool_blocks, 128>>>(h2_p, gid[g], emb, g * 128);
    }

    head_kernel<<<BB, 128>>>(emb, gma, bta, mean, var, f1W, f1b, f2W, f2b, lp);
}

// round 5
// speedup vs baseline: 2.4957x; 1.1707x over previous
#include <cuda_runtime.h>
#include <cuda_fp16.h>
#include <cstdint>

#define NN 50000
#define EE 800000
#define BB 256
#define FEAT 128
#define OUTC 10
#define EPSBN 1e-5f
#define SCAN_BLK 1024
#define NSCAN_BLOCKS ((NN + SCAN_BLK - 1) / SCAN_BLK)   // 49
#define EDGE_BLOCKS ((EE + 255) / 256)                  // 3125
#define GEMM_BPG ((NN + 127) / 128)                     // 391
#define POOL_CHUNK 64
#define POOL_BPG ((NN + POOL_CHUNK - 1) / POOL_CHUNK)   // 782
#define NTOT (3 * NN)

// ---------------- static scratch (device globals; no allocation) ----------------
__device__ __half g_hs[NTOT * FEAT];        // GEMM output (deg-scaled), fp16 gather source
__device__ float g_h1[NTOT * FEAT];         // layer-1 output (all graphs)
__device__ float g_h2[NTOT * FEAT];         // layer-2 output (all graphs)
__device__ int g_deg_out[NTOT];
__device__ int g_deg_in[NTOT];
__device__ int g_row[NTOT];                 // CSR row start (global edge index)
__device__ int g_rowend[NTOT];              // scatter bump pointer (start -> end)
__device__ int g_csr[3 * EE];               // GLOBAL src ids sorted by dst
__device__ int g_bsum[3 * NSCAN_BLOCKS];

// ---------------- batched CSR build ----------------
__global__ void degree_all_kernel(const int* __restrict__ s0, const int* __restrict__ d0,
                                  const int* __restrict__ s1, const int* __restrict__ d1,
                                  const int* __restrict__ s2, const int* __restrict__ d2)
{
    int g = blockIdx.x / EDGE_BLOCKS;
    int e = (blockIdx.x % EDGE_BLOCKS) * 256 + threadIdx.x;
    if (e >= EE) return;
    const int* src = (g == 0) ? s0 : (g == 1) ? s1 : s2;
    const int* dst = (g == 0) ? d0 : (g == 1) ? d1 : d2;
    int off = g * NN;
    atomicAdd(&g_deg_out[off + src[e]], 1);
    atomicAdd(&g_deg_in[off + dst[e]], 1);
}

// per-block local scan of deg_in; block totals -> bsum
__global__ __launch_bounds__(SCAN_BLK) void scan_local_all_kernel() {
    __shared__ int sm[SCAN_BLK];
    int b = blockIdx.x;
    int g = b / NSCAN_BLOCKS;
    int lb = b % NSCAN_BLOCKS;
    int t = threadIdx.x;
    int li = lb * SCAN_BLK + t;
    int idx = g * NN + li;
    int v = (li < NN) ? g_deg_in[idx] : 0;
    sm[t] = v;
    __syncthreads();
    #pragma unroll
    for (int off = 1; off < SCAN_BLK; off <<= 1) {
        int y = (t >= off) ? sm[t - off] : 0;
        __syncthreads();
        sm[t] += y;
        __syncthreads();
    }
    if (li < NN) g_row[idx] = sm[t] - v;
    if (t == SCAN_BLK - 1) g_bsum[b] = sm[t];
}

// add per-graph prefix of block sums; write both row (start) and rowend (bump ptr)
__global__ __launch_bounds__(SCAN_BLK) void scan_add_all_kernel() {
    __shared__ int s_off;
    int b = blockIdx.x;
    int g = b / NSCAN_BLOCKS;
    int lb = b % NSCAN_BLOCKS;
    int t = threadIdx.x;
    if (t == 0) {
        int run = 0;
        for (int i = 0; i < lb; i++) run += g_bsum[g * NSCAN_BLOCKS + i];
        s_off = run;
    }
    __syncthreads();
    int li = lb * SCAN_BLK + t;
    if (li < NN) {
        int idx = g * NN + li;
        int r = g_row[idx] + s_off;
        g_row[idx] = r;
        g_rowend[idx] = r;
    }
}

// single atomic per edge: bump rowend directly; store GLOBAL src id
__global__ void scatter_all_kernel(const int* __restrict__ s0, const int* __restrict__ d0,
                                   const int* __restrict__ s1, const int* __restrict__ d1,
                                   const int* __restrict__ s2, const int* __restrict__ d2)
{
    int g = blockIdx.x / EDGE_BLOCKS;
    int e = (blockIdx.x % EDGE_BLOCKS) * 256 + threadIdx.x;
    if (e >= EE) return;
    const int* src = (g == 0) ? s0 : (g == 1) ? s1 : s2;
    const int* dst = (g == 0) ? d0 : (g == 1) ? d1 : d2;
    int off = g * NN;
    int pos = atomicAdd(&g_rowend[off + dst[e]], 1);
    g_csr[g * EE + pos] = off + src[e];
}

// ---------------- tf32 tensor-core GEMM, fp16 output, 3-graph batched ----------------
#define A_STRIDE 36
#define W_STRIDE 136

__device__ __forceinline__ uint32_t f2tf32(float f) {
    uint32_t u;
    asm("cvt.rna.tf32.f32 %0, %1;" : "=r"(u) : "f"(f));
    return u;
}

__device__ __forceinline__ void mma_tf32(float c[4],
                                         uint32_t a0, uint32_t a1, uint32_t a2, uint32_t a3,
                                         uint32_t b0, uint32_t b1) {
    asm volatile(
        "mma.sync.aligned.m16n8k8.row.col.f32.tf32.tf32.f32 "
        "{%0,%1,%2,%3}, {%4,%5,%6,%7}, {%8,%9}, {%0,%1,%2,%3};\n"
        : "+f"(c[0]), "+f"(c[1]), "+f"(c[2]), "+f"(c[3])
        : "r"(a0), "r"(a1), "r"(a2), "r"(a3), "r"(b0), "r"(b1));
}

// grid = 3*GEMM_BPG; block b: graph gb = b/GEMM_BPG, local tile (b%GEMM_BPG)
__global__ __launch_bounds__(256) void gemm_tc_all_kernel(
    const float* __restrict__ a0p, const float* __restrict__ a1p, const float* __restrict__ a2p,
    const float* __restrict__ W, __half* __restrict__ out)
{
    __shared__ uint32_t As[128 * A_STRIDE];
    __shared__ uint32_t Ws[32 * W_STRIDE];

    int gb = blockIdx.x / GEMM_BPG;
    int lb = blockIdx.x % GEMM_BPG;
    const float* A = (gb == 0) ? a0p : (gb == 1) ? a1p : a2p;
    int goff = gb * NN;
    int row0 = lb * 128;

    int tid = threadIdx.x;
    int warp = tid >> 5;
    int lane = tid & 31;
    int g = lane >> 2;
    int tig = lane & 3;
    int warp_m = (warp >> 1) * 32;
    int warp_n = (warp & 1) * 64;

    float acc[2][8][4];
    #pragma unroll
    for (int mi = 0; mi < 2; mi++)
        #pragma unroll
        for (int ni = 0; ni < 8; ni++)
            #pragma unroll
            for (int q = 0; q < 4; q++) acc[mi][ni][q] = 0.0f;

    for (int k0 = 0; k0 < 128; k0 += 32) {
        #pragma unroll
        for (int rep = 0; rep < 4; rep++) {
            int idx = tid + rep * 256;
            int am = idx >> 3;
            int ak = (idx & 7) * 4;
            int gr = row0 + am;
            float4 av = make_float4(0.f, 0.f, 0.f, 0.f);
            if (gr < NN) av = *reinterpret_cast<const float4*>(A + (size_t)gr * 128 + k0 + ak);
            uint4 tv;
            tv.x = f2tf32(av.x); tv.y = f2tf32(av.y);
            tv.z = f2tf32(av.z); tv.w = f2tf32(av.w);
            *reinterpret_cast<uint4*>(&As[am * A_STRIDE + ak]) = tv;
        }
        #pragma unroll
        for (int rep = 0; rep < 4; rep++) {
            int idx = tid + rep * 256;
            int bk = idx >> 5;
            int bn = (idx & 31) * 4;
            float4 wv = *reinterpret_cast<const float4*>(W + (size_t)(k0 + bk) * 128 + bn);
            uint4 tv;
            tv.x = f2tf32(wv.x); tv.y = f2tf32(wv.y);
            tv.z = f2tf32(wv.z); tv.w = f2tf32(wv.w);
            *reinterpret_cast<uint4*>(&Ws[bk * W_STRIDE + bn]) = tv;
        }
        __syncthreads();

        #pragma unroll
        for (int ks = 0; ks < 4; ks++) {
            int kk = ks * 8;
            uint32_t af[2][4];
            #pragma unroll
            for (int mi = 0; mi < 2; mi++) {
                int r = warp_m + mi * 16 + g;
                af[mi][0] = As[r * A_STRIDE + kk + tig];
                af[mi][1] = As[(r + 8) * A_STRIDE + kk + tig];
                af[mi][2] = As[r * A_STRIDE + kk + tig + 4];
                af[mi][3] = As[(r + 8) * A_STRIDE + kk + tig + 4];
            }
            #pragma unroll
            for (int ni = 0; ni < 8; ni++) {
                int nc = warp_n + ni * 8 + g;
                uint32_t b0 = Ws[(kk + tig) * W_STRIDE + nc];
                uint32_t b1 = Ws[(kk + tig + 4) * W_STRIDE + nc];
                mma_tf32(acc[0][ni], af[0][0], af[0][1], af[0][2], af[0][3], b0, b1);
                mma_tf32(acc[1][ni], af[1][0], af[1][1], af[1][2], af[1][3], b0, b1);
            }
        }
        __syncthreads();
    }

    #pragma unroll
    for (int mi = 0; mi < 2; mi++) {
        int r0 = row0 + warp_m + mi * 16 + g;
        int r1 = r0 + 8;
        float rs0 = 1.f, rs1 = 1.f;
        if (r0 < NN) { int d = g_deg_out[goff + r0]; rs0 = rsqrtf((float)(d > 0 ? d : 1)); }
        if (r1 < NN) { int d = g_deg_out[goff + r1]; rs1 = rsqrtf((float)(d > 0 ? d : 1)); }
        #pragma unroll
        for (int ni = 0; ni < 8; ni++) {
            int col = warp_n + ni * 8 + tig * 2;
            if (r0 < NN) {
                __half2 v = __floats2half2_rn(acc[mi][ni][0] * rs0, acc[mi][ni][1] * rs0);
                *reinterpret_cast<__half2*>(out + (size_t)(goff + r0) * 128 + col) = v;
            }
            if (r1 < NN) {
                __half2 v = __floats2half2_rn(acc[mi][ni][2] * rs1, acc[mi][ni][3] * rs1);
                *reinterpret_cast<__half2*>(out + (size_t)(goff + r1) * 128 + col) = v;
            }
        }
    }
}

// ---------------- SpMM gather (fp16 src, fp32 accum), all graphs in one grid ----------------
// node = global warp id over NTOT; csr holds global src ids
__global__ __launch_bounds__(256) void spmm_all_kernel(const float* __restrict__ bias,
                                                       float* __restrict__ out)
{
    int node = (blockIdx.x * blockDim.x + threadIdx.x) >> 5;
    int lane = threadIdx.x & 31;
    if (node >= NTOT) return;
    int g = node / NN;
    int start = g * EE + g_row[node];
    int d = g_deg_in[node];
    const int* csr = g_csr;
    const uint2* hs8 = reinterpret_cast<const uint2*>(g_hs);
    float ax = 0.f, ay = 0.f, az = 0.f, aw = 0.f;
    int e = 0;
    for (; e + 4 <= d; e += 4) {
        int s0 = csr[start + e];
        int s1 = csr[start + e + 1];
        int s2 = csr[start + e + 2];
        int s3 = csr[start + e + 3];
        uint2 u0 = hs8[(size_t)s0 * 32 + lane];
        uint2 u1 = hs8[(size_t)s1 * 32 + lane];
        uint2 u2 = hs8[(size_t)s2 * 32 + lane];
        uint2 u3 = hs8[(size_t)s3 * 32 + lane];
        float2 a0 = __half22float2(*reinterpret_cast<__half2*>(&u0.x));
        float2 b0 = __half22float2(*reinterpret_cast<__half2*>(&u0.y));
        float2 a1 = __half22float2(*reinterpret_cast<__half2*>(&u1.x));
        float2 b1 = __half22float2(*reinterpret_cast<__half2*>(&u1.y));
        float2 a2 = __half22float2(*reinterpret_cast<__half2*>(&u2.x));
        float2 b2 = __half22float2(*reinterpret_cast<__half2*>(&u2.y));
        float2 a3 = __half22float2(*reinterpret_cast<__half2*>(&u3.x));
        float2 b3 = __half22float2(*reinterpret_cast<__half2*>(&u3.y));
        ax += (a0.x + a1.x) + (a2.x + a3.x);
        ay += (a0.y + a1.y) + (a2.y + a3.y);
        az += (b0.x + b1.x) + (b2.x + b3.x);
        aw += (b0.y + b1.y) + (b2.y + b3.y);
    }
    for (; e < d; e++) {
        int s = csr[start + e];
        uint2 u = hs8[(size_t)s * 32 + lane];
        float2 a = __half22float2(*reinterpret_cast<__half2*>(&u.x));
        float2 b = __half22float2(*reinterpret_cast<__half2*>(&u.y));
        ax += a.x; ay += a.y; az += b.x; aw += b.y;
    }
    float rs = rsqrtf((float)(d > 0 ? d : 1));
    float4 bb = reinterpret_cast<const float4*>(bias)[lane];
    float4 r;
    r.x = fmaxf(fmaf(ax, rs, bb.x), 0.f);
    r.y = fmaxf(fmaf(ay, rs, bb.y), 0.f);
    r.z = fmaxf(fmaf(az, rs, bb.z), 0.f);
    r.w = fmaxf(fmaf(aw, rs, bb.w), 0.f);
    reinterpret_cast<float4*>(out)[(size_t)node * 32 + lane] = r;
}

// ---------------- SumPooling, all graphs in one grid ----------------
__global__ void pool_all_kernel(const float* __restrict__ h2,
                                const int* __restrict__ gid0, const int* __restrict__ gid1,
                                const int* __restrict__ gid2, float* __restrict__ emb)
{
    int gb = blockIdx.x / POOL_BPG;
    int lb = blockIdx.x % POOL_BPG;
    const int* gid = (gb == 0) ? gid0 : (gb == 1) ? gid1 : gid2;
    int col_off = gb * 128;
    int goff = gb * NN;
    int f = threadIdx.x;
    int n0 = lb * POOL_CHUNK;
    int n1 = n0 + POOL_CHUNK; if (n1 > NN) n1 = NN;
    if (n0 >= NN) return;
    float local = 0.f;
    int g = gid[n0];
    for (int n = n0; n < n1; n++) {
        int gn = gid[n];
        if (gn != g) {
            atomicAdd(&emb[(size_t)g * 384 + col_off + f], local);
            local = 0.f;
            g = gn;
        }
        local += h2[(size_t)(goff + n) * 128 + f];
    }
    atomicAdd(&emb[(size_t)g * 384 + col_off + f], local);
}

// ---------------- Head: BN -> fc1 -> relu -> fc2 -> log_softmax ----------------
__global__ __launch_bounds__(128) void head_kernel(
    const float* __restrict__ emb,
    const float* __restrict__ gamma, const float* __restrict__ beta,
    const float* __restrict__ mean, const float* __restrict__ var,
    const float* __restrict__ fc1W, const float* __restrict__ fc1b,
    const float* __restrict__ fc2W, const float* __restrict__ fc2b,
    float* __restrict__ outlp)
{
    __shared__ float s[384];
    __shared__ float h[128];
    __shared__ float lg[OUTC];
    int b = blockIdx.x;
    int t = threadIdx.x;
    for (int i = t; i < 384; i += 128) {
        float v = emb[(size_t)b * 384 + i];
        s[i] = (v - mean[i]) * rsqrtf(var[i] + EPSBN) * gamma[i] + beta[i];
    }
    __syncthreads();
    float acc = fc1b[t];
    #pragma unroll 4
    for (int k = 0; k < 384; k++) acc = fmaf(s[k], fc1W[(size_t)k * 128 + t], acc);
    h[t] = fmaxf(acc, 0.f);
    __syncthreads();
    if (t < OUTC) {
        float a = fc2b[t];
        #pragma unroll 4
        for (int k = 0; k < 128; k++) a = fmaf(h[k], fc2W[(size_t)k * OUTC + t], a);
        lg[t] = a;
    }
    __syncthreads();
    if (t == 0) {
        float mx = lg[0];
        #pragma unroll
        for (int o = 1; o < OUTC; o++) mx = fmaxf(mx, lg[o]);
        float se = 0.f;
        #pragma unroll
        for (int o = 0; o < OUTC; o++) se += expf(lg[o] - mx);
        float lse = mx + logf(se);
        #pragma unroll
        for (int o = 0; o < OUTC; o++) outlp[(size_t)b * OUTC + o] = lg[o] - lse;
    }
}

// ---------------- launch ----------------
extern "C" void kernel_launch(void* const* d_in, const int* in_sizes, int n_in,
                              void* d_out, int out_size)
{
    const float* x[3];
    const int* src[3];
    const int* dst[3];
    const int* gid[3];

    if (in_sizes[1] == EE) {
        for (int g = 0; g < 3; g++) {
            x[g]   = (const float*)d_in[4 * g + 0];
            src[g] = (const int*)  d_in[4 * g + 1];
            dst[g] = (const int*)  d_in[4 * g + 2];
            gid[g] = (const int*)  d_in[4 * g + 3];
        }
    } else {
        for (int g = 0; g < 3; g++) {
            x[g]   = (const float*)d_in[g];
            src[g] = (const int*)  d_in[3 + 2 * g];
            dst[g] = (const int*)  d_in[4 + 2 * g];
            gid[g] = (const int*)  d_in[9 + g];
        }
    }
    const float* W1   = (const float*)d_in[12];
    const float* b1   = (const float*)d_in[13];
    const float* W2   = (const float*)d_in[14];
    const float* b2   = (const float*)d_in[15];
    const float* gma  = (const float*)d_in[16];
    const float* bta  = (const float*)d_in[17];
    const float* mean = (const float*)d_in[18];
    const float* var  = (const float*)d_in[19];
    const float* f1W  = (const float*)d_in[20];
    const float* f1b  = (const float*)d_in[21];
    const float* f2W  = (const float*)d_in[22];
    const float* f2b  = (const float*)d_in[23];

    float* out = (float*)d_out;
    float* emb = out;                    // [256, 384]
    float* lp  = out + (size_t)BB * 384; // [256, 10]

    __half* hs_p; float* h1_p; float* h2_p;
    void* dego_p; void* degi_p;
    cudaGetSymbolAddress((void**)&hs_p, g_hs);
    cudaGetSymbolAddress((void**)&h1_p, g_h1);
    cudaGetSymbolAddress((void**)&h2_p, g_h2);
    cudaGetSymbolAddress(&dego_p, g_deg_out);
    cudaGetSymbolAddress(&degi_p, g_deg_in);

    cudaMemsetAsync(dego_p, 0, NTOT * sizeof(int));
    cudaMemsetAsync(degi_p, 0, NTOT * sizeof(int));
    cudaMemsetAsync(emb, 0, BB * 384 * sizeof(float));

    // batched CSR build
    degree_all_kernel<<<3 * EDGE_BLOCKS, 256>>>(src[0], dst[0], src[1], dst[1], src[2], dst[2]);
    scan_local_all_kernel<<<3 * NSCAN_BLOCKS, SCAN_BLK>>>();
    scan_add_all_kernel<<<3 * NSCAN_BLOCKS, SCAN_BLK>>>();
    scatter_all_kernel<<<3 * EDGE_BLOCKS, 256>>>(src[0], dst[0], src[1], dst[1], src[2], dst[2]);

    const int spmm_blocks = (NTOT + 7) / 8;   // 8 warps/block, 150000 warps

    // layer 1 (all graphs)
    gemm_tc_all_kernel<<<3 * GEMM_BPG, 256>>>(x[0], x[1], x[2], W1, hs_p);
    spmm_all_kernel<<<spmm_blocks, 256>>>(b1, h1_p);
    // layer 2 (all graphs)
    gemm_tc_all_kernel<<<3 * GEMM_BPG, 256>>>(h1_p, h1_p + (size_t)NN * 128,
                                              h1_p + (size_t)2 * NN * 128, W2, hs_p);
    spmm_all_kernel<<<spmm_blocks, 256>>>(b2, h2_p);

    // pooling (all graphs)
    pool_all_kernel<<<3 * POOL_BPG, 128>>>(h2_p, gid[0], gid[1], gid[2], emb);

    head_kernel<<<BB, 128>>>(emb, gma, bta, mean, var, f1W, f1b, f2W, f2b, lp);
}

// round 6
// speedup vs baseline: 2.5351x; 1.0158x over previous
#include <cuda_runtime.h>
#include <cuda_fp16.h>
#include <cstdint>

#define NN 50000
#define EE 800000
#define BB 256
#define FEAT 128
#define OUTC 10
#define EPSBN 1e-5f
#define SCAN_BLK 1024
#define NSCAN_BLOCKS ((NN + SCAN_BLK - 1) / SCAN_BLK)   // 49
#define EDGE4 (EE / 4)                                  // 200000 (EE divisible by 4)
#define EDGE4_BLOCKS ((EDGE4 + 255) / 256)              // 782
#define GEMM_BPG ((NN + 127) / 128)                     // 391
#define POOL_CHUNK 64
#define POOL_BPG ((NN + POOL_CHUNK - 1) / POOL_CHUNK)   // 782
#define NTOT (3 * NN)

// ---------------- static scratch (device globals; no allocation) ----------------
__device__ __half g_hs[NTOT * FEAT];        // GEMM output (deg-scaled), fp16 gather source
__device__ __half g_h1[NTOT * FEAT];        // layer-1 output (fp16)
__device__ __half g_h2[NTOT * FEAT];        // layer-2 output (fp16)
__device__ int g_deg_out[NTOT];
__device__ int g_deg_in[NTOT];
__device__ int g_row[NTOT];                 // CSR row start (per-graph-local edge index)
__device__ int g_rowend[NTOT];              // scatter bump pointer
__device__ int g_csr[3 * EE];               // GLOBAL src ids grouped by dst
__device__ int g_bsum[3 * NSCAN_BLOCKS];

// ---------------- batched CSR build (4 edges/thread, int4 loads) ----------------
__global__ void degree_all_kernel(const int* __restrict__ s0, const int* __restrict__ d0,
                                  const int* __restrict__ s1, const int* __restrict__ d1,
                                  const int* __restrict__ s2, const int* __restrict__ d2)
{
    int g = blockIdx.x / EDGE4_BLOCKS;
    int q = (blockIdx.x % EDGE4_BLOCKS) * 256 + threadIdx.x;
    if (q >= EDGE4) return;
    const int4* src = reinterpret_cast<const int4*>((g == 0) ? s0 : (g == 1) ? s1 : s2);
    const int4* dst = reinterpret_cast<const int4*>((g == 0) ? d0 : (g == 1) ? d1 : d2);
    int off = g * NN;
    int4 s = src[q];
    int4 d = dst[q];
    atomicAdd(&g_deg_out[off + s.x], 1);
    atomicAdd(&g_deg_out[off + s.y], 1);
    atomicAdd(&g_deg_out[off + s.z], 1);
    atomicAdd(&g_deg_out[off + s.w], 1);
    atomicAdd(&g_deg_in[off + d.x], 1);
    atomicAdd(&g_deg_in[off + d.y], 1);
    atomicAdd(&g_deg_in[off + d.z], 1);
    atomicAdd(&g_deg_in[off + d.w], 1);
}

__global__ __launch_bounds__(SCAN_BLK) void scan_local_all_kernel() {
    __shared__ int sm[SCAN_BLK];
    int b = blockIdx.x;
    int g = b / NSCAN_BLOCKS;
    int lb = b % NSCAN_BLOCKS;
    int t = threadIdx.x;
    int li = lb * SCAN_BLK + t;
    int idx = g * NN + li;
    int v = (li < NN) ? g_deg_in[idx] : 0;
    sm[t] = v;
    __syncthreads();
    #pragma unroll
    for (int off = 1; off < SCAN_BLK; off <<= 1) {
        int y = (t >= off) ? sm[t - off] : 0;
        __syncthreads();
        sm[t] += y;
        __syncthreads();
    }
    if (li < NN) g_row[idx] = sm[t] - v;
    if (t == SCAN_BLK - 1) g_bsum[b] = sm[t];
}

__global__ __launch_bounds__(SCAN_BLK) void scan_add_all_kernel() {
    __shared__ int s_off;
    int b = blockIdx.x;
    int g = b / NSCAN_BLOCKS;
    int lb = b % NSCAN_BLOCKS;
    int t = threadIdx.x;
    if (t == 0) {
        int run = 0;
        for (int i = 0; i < lb; i++) run += g_bsum[g * NSCAN_BLOCKS + i];
        s_off = run;
    }
    __syncthreads();
    int li = lb * SCAN_BLK + t;
    if (li < NN) {
        int idx = g * NN + li;
        int r = g_row[idx] + s_off;
        g_row[idx] = r;
        g_rowend[idx] = r;
    }
}

__global__ void scatter_all_kernel(const int* __restrict__ s0, const int* __restrict__ d0,
                                   const int* __restrict__ s1, const int* __restrict__ d1,
                                   const int* __restrict__ s2, const int* __restrict__ d2)
{
    int g = blockIdx.x / EDGE4_BLOCKS;
    int q = (blockIdx.x % EDGE4_BLOCKS) * 256 + threadIdx.x;
    if (q >= EDGE4) return;
    const int4* src = reinterpret_cast<const int4*>((g == 0) ? s0 : (g == 1) ? s1 : s2);
    const int4* dst = reinterpret_cast<const int4*>((g == 0) ? d0 : (g == 1) ? d1 : d2);
    int off = g * NN;
    int cbase = g * EE;
    int4 s = src[q];
    int4 d = dst[q];
    int p0 = atomicAdd(&g_rowend[off + d.x], 1);
    int p1 = atomicAdd(&g_rowend[off + d.y], 1);
    int p2 = atomicAdd(&g_rowend[off + d.z], 1);
    int p3 = atomicAdd(&g_rowend[off + d.w], 1);
    g_csr[cbase + p0] = off + s.x;
    g_csr[cbase + p1] = off + s.y;
    g_csr[cbase + p2] = off + s.z;
    g_csr[cbase + p3] = off + s.w;
}

// ---------------- tf32 tensor-core GEMM, fp16 output, 3-graph batched ----------------
// templated on A element type: float (layer 1 input x) or __half (layer 2 input h1)
#define A_STRIDE 36
#define W_STRIDE 136

__device__ __forceinline__ uint32_t f2tf32(float f) {
    uint32_t u;
    asm("cvt.rna.tf32.f32 %0, %1;" : "=r"(u) : "f"(f));
    return u;
}

__device__ __forceinline__ void mma_tf32(float c[4],
                                         uint32_t a0, uint32_t a1, uint32_t a2, uint32_t a3,
                                         uint32_t b0, uint32_t b1) {
    asm volatile(
        "mma.sync.aligned.m16n8k8.row.col.f32.tf32.tf32.f32 "
        "{%0,%1,%2,%3}, {%4,%5,%6,%7}, {%8,%9}, {%0,%1,%2,%3};\n"
        : "+f"(c[0]), "+f"(c[1]), "+f"(c[2]), "+f"(c[3])
        : "r"(a0), "r"(a1), "r"(a2), "r"(a3), "r"(b0), "r"(b1));
}

template <typename AT>
__device__ __forceinline__ float4 load_a4(const AT* p);

template <>
__device__ __forceinline__ float4 load_a4<float>(const float* p) {
    return *reinterpret_cast<const float4*>(p);
}
template <>
__device__ __forceinline__ float4 load_a4<__half>(const __half* p) {
    uint2 u = *reinterpret_cast<const uint2*>(p);
    float2 lo = __half22float2(*reinterpret_cast<__half2*>(&u.x));
    float2 hi = __half22float2(*reinterpret_cast<__half2*>(&u.y));
    return make_float4(lo.x, lo.y, hi.x, hi.y);
}

template <typename AT>
__global__ __launch_bounds__(256) void gemm_tc_all_kernel(
    const AT* __restrict__ Abase, const float* __restrict__ W, __half* __restrict__ out,
    const AT* __restrict__ a0p, const AT* __restrict__ a1p, const AT* __restrict__ a2p)
{
    __shared__ uint32_t As[128 * A_STRIDE];
    __shared__ uint32_t Ws[32 * W_STRIDE];

    int gb = blockIdx.x / GEMM_BPG;
    int lb = blockIdx.x % GEMM_BPG;
    const AT* A = (gb == 0) ? a0p : (gb == 1) ? a1p : a2p;
    (void)Abase;
    int goff = gb * NN;
    int row0 = lb * 128;

    int tid = threadIdx.x;
    int warp = tid >> 5;
    int lane = tid & 31;
    int g = lane >> 2;
    int tig = lane & 3;
    int warp_m = (warp >> 1) * 32;
    int warp_n = (warp & 1) * 64;

    float acc[2][8][4];
    #pragma unroll
    for (int mi = 0; mi < 2; mi++)
        #pragma unroll
        for (int ni = 0; ni < 8; ni++)
            #pragma unroll
            for (int q = 0; q < 4; q++) acc[mi][ni][q] = 0.0f;

    for (int k0 = 0; k0 < 128; k0 += 32) {
        #pragma unroll
        for (int rep = 0; rep < 4; rep++) {
            int idx = tid + rep * 256;
            int am = idx >> 3;
            int ak = (idx & 7) * 4;
            int gr = row0 + am;
            float4 av = make_float4(0.f, 0.f, 0.f, 0.f);
            if (gr < NN) av = load_a4<AT>(A + (size_t)gr * 128 + k0 + ak);
            uint4 tv;
            tv.x = f2tf32(av.x); tv.y = f2tf32(av.y);
            tv.z = f2tf32(av.z); tv.w = f2tf32(av.w);
            *reinterpret_cast<uint4*>(&As[am * A_STRIDE + ak]) = tv;
        }
        #pragma unroll
        for (int rep = 0; rep < 4; rep++) {
            int idx = tid + rep * 256;
            int bk = idx >> 5;
            int bn = (idx & 31) * 4;
            float4 wv = *reinterpret_cast<const float4*>(W + (size_t)(k0 + bk) * 128 + bn);
            uint4 tv;
            tv.x = f2tf32(wv.x); tv.y = f2tf32(wv.y);
            tv.z = f2tf32(wv.z); tv.w = f2tf32(wv.w);
            *reinterpret_cast<uint4*>(&Ws[bk * W_STRIDE + bn]) = tv;
        }
        __syncthreads();

        #pragma unroll
        for (int ks = 0; ks < 4; ks++) {
            int kk = ks * 8;
            uint32_t af[2][4];
            #pragma unroll
            for (int mi = 0; mi < 2; mi++) {
                int r = warp_m + mi * 16 + g;
                af[mi][0] = As[r * A_STRIDE + kk + tig];
                af[mi][1] = As[(r + 8) * A_STRIDE + kk + tig];
                af[mi][2] = As[r * A_STRIDE + kk + tig + 4];
                af[mi][3] = As[(r + 8) * A_STRIDE + kk + tig + 4];
            }
            #pragma unroll
            for (int ni = 0; ni < 8; ni++) {
                int nc = warp_n + ni * 8 + g;
                uint32_t b0 = Ws[(kk + tig) * W_STRIDE + nc];
                uint32_t b1 = Ws[(kk + tig + 4) * W_STRIDE + nc];
                mma_tf32(acc[0][ni], af[0][0], af[0][1], af[0][2], af[0][3], b0, b1);
                mma_tf32(acc[1][ni], af[1][0], af[1][1], af[1][2], af[1][3], b0, b1);
            }
        }
        __syncthreads();
    }

    #pragma unroll
    for (int mi = 0; mi < 2; mi++) {
        int r0 = row0 + warp_m + mi * 16 + g;
        int r1 = r0 + 8;
        float rs0 = 1.f, rs1 = 1.f;
        if (r0 < NN) { int d = g_deg_out[goff + r0]; rs0 = rsqrtf((float)(d > 0 ? d : 1)); }
        if (r1 < NN) { int d = g_deg_out[goff + r1]; rs1 = rsqrtf((float)(d > 0 ? d : 1)); }
        #pragma unroll
        for (int ni = 0; ni < 8; ni++) {
            int col = warp_n + ni * 8 + tig * 2;
            if (r0 < NN) {
                __half2 v = __floats2half2_rn(acc[mi][ni][0] * rs0, acc[mi][ni][1] * rs0);
                *reinterpret_cast<__half2*>(out + (size_t)(goff + r0) * 128 + col) = v;
            }
            if (r1 < NN) {
                __half2 v = __floats2half2_rn(acc[mi][ni][2] * rs1, acc[mi][ni][3] * rs1);
                *reinterpret_cast<__half2*>(out + (size_t)(goff + r1) * 128 + col) = v;
            }
        }
    }
}

// ---------------- SpMM gather (fp16 src, fp32 accum, fp16 out), all graphs ----------------
__global__ __launch_bounds__(256) void spmm_all_kernel(const float* __restrict__ bias,
                                                       __half* __restrict__ out)
{
    int node = (blockIdx.x * blockDim.x + threadIdx.x) >> 5;
    int lane = threadIdx.x & 31;
    if (node >= NTOT) return;
    int g = node / NN;
    int start = g * EE + g_row[node];
    int d = g_deg_in[node];
    const int* csr = g_csr;
    const uint2* hs8 = reinterpret_cast<const uint2*>(g_hs);
    float ax = 0.f, ay = 0.f, az = 0.f, aw = 0.f;
    int e = 0;
    for (; e + 4 <= d; e += 4) {
        int s0 = csr[start + e];
        int s1 = csr[start + e + 1];
        int s2 = csr[start + e + 2];
        int s3 = csr[start + e + 3];
        uint2 u0 = hs8[(size_t)s0 * 32 + lane];
        uint2 u1 = hs8[(size_t)s1 * 32 + lane];
        uint2 u2 = hs8[(size_t)s2 * 32 + lane];
        uint2 u3 = hs8[(size_t)s3 * 32 + lane];
        float2 a0 = __half22float2(*reinterpret_cast<__half2*>(&u0.x));
        float2 b0 = __half22float2(*reinterpret_cast<__half2*>(&u0.y));
        float2 a1 = __half22float2(*reinterpret_cast<__half2*>(&u1.x));
        float2 b1 = __half22float2(*reinterpret_cast<__half2*>(&u1.y));
        float2 a2 = __half22float2(*reinterpret_cast<__half2*>(&u2.x));
        float2 b2 = __half22float2(*reinterpret_cast<__half2*>(&u2.y));
        float2 a3 = __half22float2(*reinterpret_cast<__half2*>(&u3.x));
        float2 b3 = __half22float2(*reinterpret_cast<__half2*>(&u3.y));
        ax += (a0.x + a1.x) + (a2.x + a3.x);
        ay += (a0.y + a1.y) + (a2.y + a3.y);
        az += (b0.x + b1.x) + (b2.x + b3.x);
        aw += (b0.y + b1.y) + (b2.y + b3.y);
    }
    for (; e < d; e++) {
        int s = csr[start + e];
        uint2 u = hs8[(size_t)s * 32 + lane];
        float2 a = __half22float2(*reinterpret_cast<__half2*>(&u.x));
        float2 b = __half22float2(*reinterpret_cast<__half2*>(&u.y));
        ax += a.x; ay += a.y; az += b.x; aw += b.y;
    }
    float rs = rsqrtf((float)(d > 0 ? d : 1));
    float4 bb = reinterpret_cast<const float4*>(bias)[lane];
    float rx = fmaxf(fmaf(ax, rs, bb.x), 0.f);
    float ry = fmaxf(fmaf(ay, rs, bb.y), 0.f);
    float rz = fmaxf(fmaf(az, rs, bb.z), 0.f);
    float rw = fmaxf(fmaf(aw, rs, bb.w), 0.f);
    uint2 o;
    __half2 h0 = __floats2half2_rn(rx, ry);
    __half2 h1 = __floats2half2_rn(rz, rw);
    o.x = *reinterpret_cast<uint32_t*>(&h0);
    o.y = *reinterpret_cast<uint32_t*>(&h1);
    reinterpret_cast<uint2*>(out)[(size_t)node * 32 + lane] = o;
}

// ---------------- SumPooling (fp16 input), all graphs ----------------
__global__ void pool_all_kernel(const __half* __restrict__ h2,
                                const int* __restrict__ gid0, const int* __restrict__ gid1,
                                const int* __restrict__ gid2, float* __restrict__ emb)
{
    int gb = blockIdx.x / POOL_BPG;
    int lb = blockIdx.x % POOL_BPG;
    const int* gid = (gb == 0) ? gid0 : (gb == 1) ? gid1 : gid2;
    int col_off = gb * 128;
    int goff = gb * NN;
    int f = threadIdx.x;
    int n0 = lb * POOL_CHUNK;
    int n1 = n0 + POOL_CHUNK; if (n1 > NN) n1 = NN;
    if (n0 >= NN) return;
    float local = 0.f;
    int g = gid[n0];
    for (int n = n0; n < n1; n++) {
        int gn = gid[n];
        if (gn != g) {
            atomicAdd(&emb[(size_t)g * 384 + col_off + f], local);
            local = 0.f;
            g = gn;
        }
        local += __half2float(h2[(size_t)(goff + n) * 128 + f]);
    }
    atomicAdd(&emb[(size_t)g * 384 + col_off + f], local);
}

// ---------------- Head: BN -> fc1 -> relu -> fc2 -> log_softmax ----------------
__global__ __launch_bounds__(128) void head_kernel(
    const float* __restrict__ emb,
    const float* __restrict__ gamma, const float* __restrict__ beta,
    const float* __restrict__ mean, const float* __restrict__ var,
    const float* __restrict__ fc1W, const float* __restrict__ fc1b,
    const float* __restrict__ fc2W, const float* __restrict__ fc2b,
    float* __restrict__ outlp)
{
    __shared__ float s[384];
    __shared__ float h[128];
    __shared__ float lg[OUTC];
    int b = blockIdx.x;
    int t = threadIdx.x;
    for (int i = t; i < 384; i += 128) {
        float v = emb[(size_t)b * 384 + i];
        s[i] = (v - mean[i]) * rsqrtf(var[i] + EPSBN) * gamma[i] + beta[i];
    }
    __syncthreads();
    float acc = fc1b[t];
    #pragma unroll 4
    for (int k = 0; k < 384; k++) acc = fmaf(s[k], fc1W[(size_t)k * 128 + t], acc);
    h[t] = fmaxf(acc, 0.f);
    __syncthreads();
    if (t < OUTC) {
        float a = fc2b[t];
        #pragma unroll 4
        for (int k = 0; k < 128; k++) a = fmaf(h[k], fc2W[(size_t)k * OUTC + t], a);
        lg[t] = a;
    }
    __syncthreads();
    if (t == 0) {
        float mx = lg[0];
        #pragma unroll
        for (int o = 1; o < OUTC; o++) mx = fmaxf(mx, lg[o]);
        float se = 0.f;
        #pragma unroll
        for (int o = 0; o < OUTC; o++) se += expf(lg[o] - mx);
        float lse = mx + logf(se);
        #pragma unroll
        for (int o = 0; o < OUTC; o++) outlp[(size_t)b * OUTC + o] = lg[o] - lse;
    }
}

// ---------------- launch ----------------
extern "C" void kernel_launch(void* const* d_in, const int* in_sizes, int n_in,
                              void* d_out, int out_size)
{
    const float* x[3];
    const int* src[3];
    const int* dst[3];
    const int* gid[3];

    if (in_sizes[1] == EE) {
        for (int g = 0; g < 3; g++) {
            x[g]   = (const float*)d_in[4 * g + 0];
            src[g] = (const int*)  d_in[4 * g + 1];
            dst[g] = (const int*)  d_in[4 * g + 2];
            gid[g] = (const int*)  d_in[4 * g + 3];
        }
    } else {
        for (int g = 0; g < 3; g++) {
            x[g]   = (const float*)d_in[g];
            src[g] = (const int*)  d_in[3 + 2 * g];
            dst[g] = (const int*)  d_in[4 + 2 * g];
            gid[g] = (const int*)  d_in[9 + g];
        }
    }
    const float* W1   = (const float*)d_in[12];
    const float* b1   = (const float*)d_in[13];
    const float* W2   = (const float*)d_in[14];
    const float* b2   = (const float*)d_in[15];
    const float* gma  = (const float*)d_in[16];
    const float* bta  = (const float*)d_in[17];
    const float* mean = (const float*)d_in[18];
    const float* var  = (const float*)d_in[19];
    const float* f1W  = (const float*)d_in[20];
    const float* f1b  = (const float*)d_in[21];
    const float* f2W  = (const float*)d_in[22];
    const float* f2b  = (const float*)d_in[23];

    float* out = (float*)d_out;
    float* emb = out;                    // [256, 384]
    float* lp  = out + (size_t)BB * 384; // [256, 10]

    __half* hs_p; __half* h1_p; __half* h2_p;
    void* dego_p; void* degi_p;
    cudaGetSymbolAddress((void**)&hs_p, g_hs);
    cudaGetSymbolAddress((void**)&h1_p, g_h1);
    cudaGetSymbolAddress((void**)&h2_p, g_h2);
    cudaGetSymbolAddress(&dego_p, g_deg_out);
    cudaGetSymbolAddress(&degi_p, g_deg_in);

    cudaMemsetAsync(dego_p, 0, NTOT * sizeof(int));
    cudaMemsetAsync(degi_p, 0, NTOT * sizeof(int));
    cudaMemsetAsync(emb, 0, BB * 384 * sizeof(float));

    // batched CSR build
    degree_all_kernel<<<3 * EDGE4_BLOCKS, 256>>>(src[0], dst[0], src[1], dst[1], src[2], dst[2]);
    scan_local_all_kernel<<<3 * NSCAN_BLOCKS, SCAN_BLK>>>();
    scan_add_all_kernel<<<3 * NSCAN_BLOCKS, SCAN_BLK>>>();
    scatter_all_kernel<<<3 * EDGE4_BLOCKS, 256>>>(src[0], dst[0], src[1], dst[1], src[2], dst[2]);

    const int spmm_blocks = (NTOT + 7) / 8;   // 8 warps/block

    // layer 1 (all graphs): A = x (fp32)
    gemm_tc_all_kernel<float><<<3 * GEMM_BPG, 256>>>(x[0], W1, hs_p, x[0], x[1], x[2]);
    spmm_all_kernel<<<spmm_blocks, 256>>>(b1, h1_p);
    // layer 2 (all graphs): A = h1 (fp16)
    gemm_tc_all_kernel<__half><<<3 * GEMM_BPG, 256>>>(h1_p, W2, hs_p,
                                                      h1_p, h1_p + (size_t)NN * 128,
                                                      h1_p + (size_t)2 * NN * 128);
    spmm_all_kernel<<<spmm_blocks, 256>>>(b2, h2_p);

    // pooling (all graphs)
    pool_all_kernel<<<3 * POOL_BPG, 128>>>(h2_p, gid[0], gid[1], gid[2], emb);

    head_kernel<<<BB, 128>>>(emb, gma, bta, mean, var, f1W, f1b, f2W, f2b, lp);
}